// round 2
// baseline (speedup 1.0000x reference)
#include <cuda_runtime.h>
#include <cstdint>
#include <math.h>

// ---------------------------------------------------------------------------
// HyenaOperator2d:  B=4, S=128, D=256, d3=768, L=16384, FO=64
// Pipeline:
//   filter_kernel : hx,hy (implicit MLP filters * decay), hx scaled by 1/256
//   gemm1_kernel  : U = x @ in_w + in_b       -> planar (b, c, l)   192MB
//   dwconv_kernel : depthwise 3x3 (taps -2..0), split, vg = v*x1    -> planar
//   pass1_kernel  : W1[h][j] = sum_i vg[h][i] * hy[j-i]   (Toeplitz right-mult)
//   pass2_kernel  : C[i][j]  = sum_h hx[i-h] * W1[h][j];  g=(C+vg*fb)*x0
//   gemm2_kernel  : out = g @ out_w + out_b   (A is K-major planar)
// ---------------------------------------------------------------------------

#define PI_F 3.14159265358979f
// ln(0.01)/1.5 , ln(0.01)/0.3
#define MIN_D (-3.0701134573253943f)
#define MAX_D (-15.350567286626972f)

__device__ float g_hxT[256 * 128];            // [d][s], includes *dec*(1/256)
__device__ float g_hyT[256 * 128];            // [d][s], includes *dec
__device__ float g_U [50331648];              // (b,768,16384) planar
__device__ float g_x0[16777216];              // (b,256,16384) planar
__device__ float g_vg[16777216];
__device__ float g_w1[16777216];
__device__ float g_g [16777216];

// ---------------------------------------------------------------------------
// Implicit filter MLPs + positional embedding + decay. 128 blocks (s), 64 thr.
// ---------------------------------------------------------------------------
__global__ void filter_kernel(
    const float* __restrict__ freq,
    const float* __restrict__ xw0, const float* __restrict__ xb0,
    const float* __restrict__ xw1, const float* __restrict__ xb1,
    const float* __restrict__ xw2, const float* __restrict__ xb2,
    const float* __restrict__ xw3,
    const float* __restrict__ yw0, const float* __restrict__ yb0,
    const float* __restrict__ yw1, const float* __restrict__ yb1,
    const float* __restrict__ yw2, const float* __restrict__ yb2,
    const float* __restrict__ yw3)
{
    __shared__ float h[64];
    const int s = blockIdx.x;      // 0..127
    const int j = threadIdx.x;     // 0..63

    const float t   = (float)s / 127.0f;
    const float phi = 1e-4f * 2.0f * PI_F * (float)s / 128.0f;
    const float z0 = t, z1 = cosf(phi), z2 = -sinf(phi);
    const float fr = freq[j];

    for (int which = 0; which < 2; which++) {
        const float* w0 = which ? yw0 : xw0;  const float* b0 = which ? yb0 : xb0;
        const float* w1 = which ? yw1 : xw1;  const float* b1 = which ? yb1 : xb1;
        const float* w2 = which ? yw2 : xw2;  const float* b2 = which ? yb2 : xb2;
        const float* w3 = which ? yw3 : xw3;

        float v = z0 * w0[j] + z1 * w0[64 + j] + z2 * w0[128 + j] + b0[j];
        h[j] = sinf(fr * v);
        __syncthreads();

        float a = b1[j];
        #pragma unroll 8
        for (int k = 0; k < 64; k++) a += h[k] * w1[k * 64 + j];
        __syncthreads();
        h[j] = sinf(fr * a);
        __syncthreads();

        a = b2[j];
        #pragma unroll 8
        for (int k = 0; k < 64; k++) a += h[k] * w2[k * 64 + j];
        __syncthreads();
        h[j] = sinf(fr * a);
        __syncthreads();

        float o[4] = {0.f, 0.f, 0.f, 0.f};
        #pragma unroll 8
        for (int k = 0; k < 64; k++) {
            float hv = h[k];
            #pragma unroll
            for (int r = 0; r < 4; r++) o[r] += hv * w3[k * 256 + j + 64 * r];
        }
        #pragma unroll
        for (int r = 0; r < 4; r++) {
            int d = j + 64 * r;
            float delta = MIN_D + (MAX_D - MIN_D) * ((float)d / 255.0f);
            float dec = expf(-t * fabsf(delta));
            if (which == 0)
                g_hxT[d * 128 + s] = o[r] * dec * (1.0f / 256.0f); // fold fft 1/n
            else
                g_hyT[d * 128 + s] = o[r] * dec;
        }
        __syncthreads();   // h reused by second filter
    }
}

// ---------------------------------------------------------------------------
// GEMM1: U(b,c,l) = x(b,l,k) @ in_w(k,c) + in_b.  M=65536 K=256 N=768.
// BM=BN=128, BK=8, 256 threads, 8x8 micro-tiles (interleaved, lanes along m).
// ---------------------------------------------------------------------------
__global__ __launch_bounds__(256) void gemm1_kernel(
    const float* __restrict__ X, const float* __restrict__ W,
    const float* __restrict__ bias)
{
    __shared__ __align__(16) float As[8 * 128];
    __shared__ __align__(16) float Bs[8 * 128];
    const int m0 = blockIdx.x * 128;
    const int n0 = blockIdx.y * 128;
    const int tid = threadIdx.x;
    const int tm = tid & 15;        // lanes vary along m (planar writes coalesce)
    const int tn = tid >> 4;
    const int arow = tid >> 1, ak4 = (tid & 1) * 4;
    const int brow = tid >> 5, bn4 = (tid & 31) * 4;

    float acc[8][8];
    #pragma unroll
    for (int i = 0; i < 8; i++)
        #pragma unroll
        for (int j = 0; j < 8; j++) acc[i][j] = 0.f;

    const float* Aptr = X + (size_t)(m0 + arow) * 256 + ak4;
    for (int k0 = 0; k0 < 256; k0 += 8) {
        float4 av = *(const float4*)(Aptr + k0);
        As[(ak4 + 0) * 128 + arow] = av.x;
        As[(ak4 + 1) * 128 + arow] = av.y;
        As[(ak4 + 2) * 128 + arow] = av.z;
        As[(ak4 + 3) * 128 + arow] = av.w;
        float4 bv = *(const float4*)(W + (size_t)(k0 + brow) * 768 + n0 + bn4);
        *(float4*)(&Bs[brow * 128 + bn4]) = bv;
        __syncthreads();
        #pragma unroll
        for (int k = 0; k < 8; k++) {
            float ar[8], br[8];
            #pragma unroll
            for (int i = 0; i < 8; i++) ar[i] = As[k * 128 + tm + 16 * i];
            #pragma unroll
            for (int j = 0; j < 8; j++) br[j] = Bs[k * 128 + tn + 16 * j];
            #pragma unroll
            for (int i = 0; i < 8; i++)
                #pragma unroll
                for (int j = 0; j < 8; j++) acc[i][j] += ar[i] * br[j];
        }
        __syncthreads();
    }
    const int b  = m0 >> 14;
    const int l0 = m0 & 16383;
    #pragma unroll
    for (int j = 0; j < 8; j++) {
        int n = n0 + tn + 16 * j;
        float bb = bias[n];
        float* op = g_U + ((size_t)(b * 768 + n) << 14) + l0 + tm;
        #pragma unroll
        for (int i = 0; i < 8; i++) op[16 * i] = acc[i][j] + bb;
    }
}

// ---------------------------------------------------------------------------
// Depthwise 3x3 conv (taps at offsets -2..0), split x0/x1/v, vg = v*x1.
// Block per (b,d). Threads 0-127: x0 plane; 128-255: x1 & v planes -> vg.
// Sliding column window down rows; reads rely on L1.
// ---------------------------------------------------------------------------
__global__ __launch_bounds__(256) void dwconv_kernel(
    const float* __restrict__ sfw, const float* __restrict__ sfb)
{
    const int bd = blockIdx.x;          // b*256 + d
    const int b = bd >> 8, d = bd & 255;
    const int tid = threadIdx.x;
    const int j = tid & 127;
    const size_t outp = (size_t)bd << 14;

    if (tid < 128) {
        const float* p = g_U + ((size_t)(b * 768 + d) << 14);
        float w[9];
        #pragma unroll
        for (int q = 0; q < 9; q++) w[q] = sfw[d * 9 + q];
        const float bs = sfb[d];
        float a0 = 0, a1 = 0, a2 = 0, r0 = 0, r1 = 0, r2 = 0;
        for (int i = 0; i < 128; i++) {
            const float* row = p + i * 128;
            float c0 = (j >= 2) ? row[j - 2] : 0.f;
            float c1 = (j >= 1) ? row[j - 1] : 0.f;
            float c2 = row[j];
            float acc = bs + w[0]*a0 + w[1]*a1 + w[2]*a2
                           + w[3]*r0 + w[4]*r1 + w[5]*r2
                           + w[6]*c0 + w[7]*c1 + w[8]*c2;
            g_x0[outp + i * 128 + j] = acc;
            a0 = r0; a1 = r1; a2 = r2; r0 = c0; r1 = c1; r2 = c2;
        }
    } else {
        const float* p1 = g_U + ((size_t)(b * 768 + 256 + d) << 14); // x1 src
        const float* p2 = g_U + ((size_t)(b * 768 + 512 + d) << 14); // v  src
        float w1[9], w2[9];
        #pragma unroll
        for (int q = 0; q < 9; q++) {
            w1[q] = sfw[(256 + d) * 9 + q];
            w2[q] = sfw[(512 + d) * 9 + q];
        }
        const float bs1 = sfb[256 + d], bs2 = sfb[512 + d];
        float a10=0,a11=0,a12=0, r10=0,r11=0,r12=0;
        float a20=0,a21=0,a22=0, r20=0,r21=0,r22=0;
        for (int i = 0; i < 128; i++) {
            const float* row1 = p1 + i * 128;
            const float* row2 = p2 + i * 128;
            float c10 = (j >= 2) ? row1[j - 2] : 0.f;
            float c11 = (j >= 1) ? row1[j - 1] : 0.f;
            float c12 = row1[j];
            float c20 = (j >= 2) ? row2[j - 2] : 0.f;
            float c21 = (j >= 1) ? row2[j - 1] : 0.f;
            float c22 = row2[j];
            float x1v = bs1 + w1[0]*a10 + w1[1]*a11 + w1[2]*a12
                            + w1[3]*r10 + w1[4]*r11 + w1[5]*r12
                            + w1[6]*c10 + w1[7]*c11 + w1[8]*c12;
            float vv  = bs2 + w2[0]*a20 + w2[1]*a21 + w2[2]*a22
                            + w2[3]*r20 + w2[4]*r21 + w2[5]*r22
                            + w2[6]*c20 + w2[7]*c21 + w2[8]*c22;
            g_vg[outp + i * 128 + j] = vv * x1v;
            a10=r10; a11=r11; a12=r12; r10=c10; r11=c11; r12=c12;
            a20=r20; a21=r21; a22=r22; r20=c20; r21=c21; r22=c22;
        }
    }
}

// ---------------------------------------------------------------------------
// Pass 1: per (b,d) plane, W1 = VG @ T(hy)   (causal Toeplitz along width)
// ---------------------------------------------------------------------------
__global__ __launch_bounds__(256) void pass1_kernel()
{
    __shared__ __align__(16) float As[8 * 128];
    __shared__ __align__(16) float Ts[8 * 128];
    __shared__ float hys[128];
    const int bd = blockIdx.x;
    const int d = bd & 255;
    const float* A = g_vg + ((size_t)bd << 14);
    float* C = g_w1 + ((size_t)bd << 14);
    const int tid = threadIdx.x;
    if (tid < 128) hys[tid] = g_hyT[d * 128 + tid];
    const int tn = tid & 15, tm = tid >> 4;   // lanes vary n (row-major writes)
    const int arow = tid >> 1, ak4 = (tid & 1) * 4;

    float acc[8][8];
    #pragma unroll
    for (int i = 0; i < 8; i++)
        #pragma unroll
        for (int j = 0; j < 8; j++) acc[i][j] = 0.f;
    __syncthreads();

    for (int k0 = 0; k0 < 128; k0 += 8) {
        float4 av = *(const float4*)(A + arow * 128 + k0 + ak4);
        As[(ak4 + 0) * 128 + arow] = av.x;
        As[(ak4 + 1) * 128 + arow] = av.y;
        As[(ak4 + 2) * 128 + arow] = av.z;
        As[(ak4 + 3) * 128 + arow] = av.w;
        #pragma unroll
        for (int c = 0; c < 4; c++) {
            int e = tid * 4 + c;
            int ki = e >> 7, jj = e & 127;
            int lag = jj - k0 - ki;
            Ts[e] = (lag >= 0) ? hys[lag] : 0.f;
        }
        __syncthreads();
        #pragma unroll
        for (int k = 0; k < 8; k++) {
            float ar[8], tr[8];
            #pragma unroll
            for (int i = 0; i < 8; i++) ar[i] = As[k * 128 + tm + 16 * i];
            #pragma unroll
            for (int j = 0; j < 8; j++) tr[j] = Ts[k * 128 + tn + 16 * j];
            #pragma unroll
            for (int i = 0; i < 8; i++)
                #pragma unroll
                for (int j = 0; j < 8; j++) acc[i][j] += ar[i] * tr[j];
        }
        __syncthreads();
    }
    #pragma unroll
    for (int i = 0; i < 8; i++)
        #pragma unroll
        for (int j = 0; j < 8; j++)
            C[(tm + 16 * i) * 128 + tn + 16 * j] = acc[i][j];
}

// ---------------------------------------------------------------------------
// Pass 2: C = T(hx) @ W1 ;  g = (C + vg*fbias[d]) * x0   (per (b,d) plane)
// ---------------------------------------------------------------------------
__global__ __launch_bounds__(256) void pass2_kernel(const float* __restrict__ fbias)
{
    __shared__ __align__(16) float Ts[8 * 128];
    __shared__ __align__(16) float Bs[8 * 128];
    __shared__ float hxs[128];
    const int bd = blockIdx.x;
    const int d = bd & 255;
    const float* Bp  = g_w1 + ((size_t)bd << 14);
    const float* vgp = g_vg + ((size_t)bd << 14);
    const float* x0p = g_x0 + ((size_t)bd << 14);
    float* Cp = g_g + ((size_t)bd << 14);
    const int tid = threadIdx.x;
    if (tid < 128) hxs[tid] = g_hxT[d * 128 + tid];
    const int tn = tid & 15, tm = tid >> 4;
    const int bkr = tid >> 5, bn4 = (tid & 31) * 4;

    float acc[8][8];
    #pragma unroll
    for (int i = 0; i < 8; i++)
        #pragma unroll
        for (int j = 0; j < 8; j++) acc[i][j] = 0.f;
    __syncthreads();

    for (int k0 = 0; k0 < 128; k0 += 8) {
        #pragma unroll
        for (int c = 0; c < 4; c++) {
            int e = tid * 4 + c;
            int ki = e >> 7, mm = e & 127;
            int lag = mm - k0 - ki;
            Ts[e] = (lag >= 0) ? hxs[lag] : 0.f;
        }
        float4 bv = *(const float4*)(Bp + (k0 + bkr) * 128 + bn4);
        *(float4*)(&Bs[bkr * 128 + bn4]) = bv;
        __syncthreads();
        #pragma unroll
        for (int k = 0; k < 8; k++) {
            float ar[8], br[8];
            #pragma unroll
            for (int i = 0; i < 8; i++) ar[i] = Ts[k * 128 + tm + 16 * i];
            #pragma unroll
            for (int j = 0; j < 8; j++) br[j] = Bs[k * 128 + tn + 16 * j];
            #pragma unroll
            for (int i = 0; i < 8; i++)
                #pragma unroll
                for (int j = 0; j < 8; j++) acc[i][j] += ar[i] * br[j];
        }
        __syncthreads();
    }
    const float fb = fbias[d];
    #pragma unroll
    for (int i = 0; i < 8; i++)
        #pragma unroll
        for (int j = 0; j < 8; j++) {
            int idx = (tm + 16 * i) * 128 + tn + 16 * j;
            Cp[idx] = (acc[i][j] + vgp[idx] * fb) * x0p[idx];
        }
}

// ---------------------------------------------------------------------------
// GEMM2: out(b,l,n) = g(b,d,l)^T @ out_w(d,n) + out_b.  A is K-major planar.
// ---------------------------------------------------------------------------
__global__ __launch_bounds__(256) void gemm2_kernel(
    const float* __restrict__ W, const float* __restrict__ bias,
    float* __restrict__ Out)
{
    __shared__ __align__(16) float As[8 * 128];
    __shared__ __align__(16) float Bs[8 * 128];
    const int m0 = blockIdx.x * 128;
    const int n0 = blockIdx.y * 128;
    const int b  = blockIdx.z;
    const int tid = threadIdx.x;
    const int tn = tid & 15, tm = tid >> 4;   // lanes vary n (row-major out)
    const int akr = tid >> 5, am4 = (tid & 31) * 4;

    float acc[8][8];
    #pragma unroll
    for (int i = 0; i < 8; i++)
        #pragma unroll
        for (int j = 0; j < 8; j++) acc[i][j] = 0.f;

    const float* Ab = g_g + ((size_t)b << 22);
    for (int k0 = 0; k0 < 256; k0 += 8) {
        float4 av = *(const float4*)(Ab + ((size_t)(k0 + akr) << 14) + m0 + am4);
        *(float4*)(&As[akr * 128 + am4]) = av;
        float4 bv = *(const float4*)(W + (size_t)(k0 + akr) * 256 + n0 + am4);
        *(float4*)(&Bs[akr * 128 + am4]) = bv;
        __syncthreads();
        #pragma unroll
        for (int k = 0; k < 8; k++) {
            float ar[8], br[8];
            #pragma unroll
            for (int i = 0; i < 8; i++) ar[i] = As[k * 128 + tm + 16 * i];
            #pragma unroll
            for (int j = 0; j < 8; j++) br[j] = Bs[k * 128 + tn + 16 * j];
            #pragma unroll
            for (int i = 0; i < 8; i++)
                #pragma unroll
                for (int j = 0; j < 8; j++) acc[i][j] += ar[i] * br[j];
        }
        __syncthreads();
    }
    #pragma unroll
    for (int j = 0; j < 8; j++) {
        int n = n0 + tn + 16 * j;
        float bb = bias[n];
        #pragma unroll
        for (int i = 0; i < 8; i++) {
            int m = m0 + tm + 16 * i;
            Out[(((size_t)b << 14) + m) * 256 + n] = acc[i][j] + bb;
        }
    }
}

// ---------------------------------------------------------------------------
extern "C" void kernel_launch(void* const* d_in, const int* in_sizes, int n_in,
                              void* d_out, int out_size)
{
    (void)in_sizes; (void)n_in; (void)out_size;
    const float* x     = (const float*)d_in[0];
    const float* in_w  = (const float*)d_in[1];
    const float* in_b  = (const float*)d_in[2];
    const float* out_w = (const float*)d_in[3];
    const float* out_b = (const float*)d_in[4];
    const float* sf_w  = (const float*)d_in[5];
    const float* sf_b  = (const float*)d_in[6];
    const float* freq  = (const float*)d_in[7];
    const float* xw0 = (const float*)d_in[8];
    const float* xb0 = (const float*)d_in[9];
    const float* xw1 = (const float*)d_in[10];
    const float* xb1 = (const float*)d_in[11];
    const float* xw2 = (const float*)d_in[12];
    const float* xb2 = (const float*)d_in[13];
    const float* xw3 = (const float*)d_in[14];
    const float* yw0 = (const float*)d_in[15];
    const float* yb0 = (const float*)d_in[16];
    const float* yw1 = (const float*)d_in[17];
    const float* yb1 = (const float*)d_in[18];
    const float* yw2 = (const float*)d_in[19];
    const float* yb2 = (const float*)d_in[20];
    const float* yw3 = (const float*)d_in[21];
    const float* fbias = (const float*)d_in[22];
    float* out = (float*)d_out;

    filter_kernel<<<128, 64>>>(freq, xw0, xb0, xw1, xb1, xw2, xb2, xw3,
                               yw0, yb0, yw1, yb1, yw2, yb2, yw3);
    dim3 g1(512, 6);
    gemm1_kernel<<<g1, 256>>>(x, in_w, in_b);
    dwconv_kernel<<<1024, 256>>>(sf_w, sf_b);
    pass1_kernel<<<1024, 256>>>();
    pass2_kernel<<<1024, 256>>>(fbias);
    dim3 g2(128, 2, 4);
    gemm2_kernel<<<g2, 256>>>(out_w, out_b, out);
}

// round 3
// speedup vs baseline: 1.1206x; 1.1206x over previous
#include <cuda_runtime.h>
#include <cstdint>
#include <math.h>

// ---------------------------------------------------------------------------
// HyenaOperator2d:  B=4, S=128, D=256, d3=768, L=16384, FO=64
//   filter_kernel : hx,hy (implicit MLP filters * decay), hx scaled by 1/256
//   gemm1_kernel  : U = x @ in_w + in_b       -> planar (b, c, l)  [FFMA2]
//   dwconv_kernel : depthwise 3x3 (taps -2..0), split, vg = v*x1   -> planar
//   toep_kernel   : fused W1 = vg @ T(hy);  g = (T(hx)@W1 + vg*fb)*x0 [FFMA2]
//   gemm2_kernel  : out = g^T @ out_w + out_b                      [FFMA2]
// ---------------------------------------------------------------------------

#define PI_F 3.14159265358979f
#define MIN_D (-3.0701134573253943f)
#define MAX_D (-15.350567286626972f)

__device__ float g_hxT[256 * 128];            // [d][s], includes *dec*(1/256)
__device__ float g_hyT[256 * 128];            // [d][s], includes *dec
__device__ float g_U [50331648];              // (b,768,16384) planar
__device__ float g_x0[16777216];              // (b,256,16384) planar
__device__ float g_vg[16777216];
__device__ float g_g [16777216];

// ---- f32x2 packed-FMA helpers (sm_103a FFMA2 path) ------------------------
__device__ __forceinline__ unsigned long long bcast2(float v) {
    unsigned long long r;
    asm("mov.b64 %0, {%1,%1};" : "=l"(r) : "f"(v));
    return r;
}
__device__ __forceinline__ void ffma2(unsigned long long& acc,
                                      unsigned long long a,
                                      unsigned long long b) {
    asm("fma.rn.f32x2 %0, %1, %2, %0;" : "+l"(acc) : "l"(a), "l"(b));
}
__device__ __forceinline__ float2 unpack2(unsigned long long v) {
    float2 r;
    asm("mov.b64 {%0,%1}, %2;" : "=f"(r.x), "=f"(r.y) : "l"(v));
    return r;
}

// ---------------------------------------------------------------------------
// Implicit filter MLPs + positional embedding + decay. 128 blocks (s), 64 thr.
// ---------------------------------------------------------------------------
__global__ void filter_kernel(
    const float* __restrict__ freq,
    const float* __restrict__ xw0, const float* __restrict__ xb0,
    const float* __restrict__ xw1, const float* __restrict__ xb1,
    const float* __restrict__ xw2, const float* __restrict__ xb2,
    const float* __restrict__ xw3,
    const float* __restrict__ yw0, const float* __restrict__ yb0,
    const float* __restrict__ yw1, const float* __restrict__ yb1,
    const float* __restrict__ yw2, const float* __restrict__ yb2,
    const float* __restrict__ yw3)
{
    __shared__ float h[64];
    const int s = blockIdx.x;      // 0..127
    const int j = threadIdx.x;     // 0..63

    const float t   = (float)s / 127.0f;
    const float phi = 1e-4f * 2.0f * PI_F * (float)s / 128.0f;
    const float z0 = t, z1 = cosf(phi), z2 = -sinf(phi);
    const float fr = freq[j];

    for (int which = 0; which < 2; which++) {
        const float* w0 = which ? yw0 : xw0;  const float* b0 = which ? yb0 : xb0;
        const float* w1 = which ? yw1 : xw1;  const float* b1 = which ? yb1 : xb1;
        const float* w2 = which ? yw2 : xw2;  const float* b2 = which ? yb2 : xb2;
        const float* w3 = which ? yw3 : xw3;

        float v = z0 * w0[j] + z1 * w0[64 + j] + z2 * w0[128 + j] + b0[j];
        h[j] = sinf(fr * v);
        __syncthreads();

        float a = b1[j];
        #pragma unroll 8
        for (int k = 0; k < 64; k++) a += h[k] * w1[k * 64 + j];
        __syncthreads();
        h[j] = sinf(fr * a);
        __syncthreads();

        a = b2[j];
        #pragma unroll 8
        for (int k = 0; k < 64; k++) a += h[k] * w2[k * 64 + j];
        __syncthreads();
        h[j] = sinf(fr * a);
        __syncthreads();

        float o[4] = {0.f, 0.f, 0.f, 0.f};
        #pragma unroll 8
        for (int k = 0; k < 64; k++) {
            float hv = h[k];
            #pragma unroll
            for (int r = 0; r < 4; r++) o[r] += hv * w3[k * 256 + j + 64 * r];
        }
        #pragma unroll
        for (int r = 0; r < 4; r++) {
            int d = j + 64 * r;
            float delta = MIN_D + (MAX_D - MIN_D) * ((float)d / 255.0f);
            float dec = expf(-t * fabsf(delta));
            if (which == 0)
                g_hxT[d * 128 + s] = o[r] * dec * (1.0f / 256.0f); // fold fft 1/n
            else
                g_hyT[d * 128 + s] = o[r] * dec;
        }
        __syncthreads();   // h reused by second filter
    }
}

// ---------------------------------------------------------------------------
// GEMM1: U(b,c,l) = x(b,l,k) @ in_w(k,c) + in_b.  M=65536 K=256 N=768.
// BM=BN=128, BK=8, 256 thr. FFMA2: pairs along m (matches planar l stores).
// Thread tile: m = 2*tm + 32*i + {0,1} (i<4 pairs), n = tn + 16*j (j<8).
// ---------------------------------------------------------------------------
__global__ __launch_bounds__(256) void gemm1_kernel(
    const float* __restrict__ X, const float* __restrict__ W,
    const float* __restrict__ bias)
{
    __shared__ __align__(16) float As[8 * 128];
    __shared__ __align__(16) float Bs[8 * 128];
    const int m0 = blockIdx.x * 128;
    const int n0 = blockIdx.y * 128;
    const int tid = threadIdx.x;
    const int tm = tid & 15;
    const int tn = tid >> 4;
    const int arow = tid >> 1, ak4 = (tid & 1) * 4;
    const int brow = tid >> 5, bn4 = (tid & 31) * 4;

    unsigned long long acc2[4][8];
    #pragma unroll
    for (int i = 0; i < 4; i++)
        #pragma unroll
        for (int j = 0; j < 8; j++) acc2[i][j] = 0ULL;

    const float* Aptr = X + (size_t)(m0 + arow) * 256 + ak4;
    for (int k0 = 0; k0 < 256; k0 += 8) {
        float4 av = *(const float4*)(Aptr + k0);
        As[(ak4 + 0) * 128 + arow] = av.x;
        As[(ak4 + 1) * 128 + arow] = av.y;
        As[(ak4 + 2) * 128 + arow] = av.z;
        As[(ak4 + 3) * 128 + arow] = av.w;
        float4 bv = *(const float4*)(W + (size_t)(k0 + brow) * 768 + n0 + bn4);
        *(float4*)(&Bs[brow * 128 + bn4]) = bv;
        __syncthreads();
        #pragma unroll
        for (int k = 0; k < 8; k++) {
            unsigned long long a2[4];
            #pragma unroll
            for (int i = 0; i < 4; i++)
                a2[i] = *(const unsigned long long*)&As[k * 128 + 2 * tm + 32 * i];
            #pragma unroll
            for (int j = 0; j < 8; j++) {
                unsigned long long b2 = bcast2(Bs[k * 128 + tn + 16 * j]);
                #pragma unroll
                for (int i = 0; i < 4; i++) ffma2(acc2[i][j], a2[i], b2);
            }
        }
        __syncthreads();
    }
    const int b  = m0 >> 14;
    const int l0 = m0 & 16383;
    #pragma unroll
    for (int j = 0; j < 8; j++) {
        int n = n0 + tn + 16 * j;
        float bb = bias[n];
        float* op = g_U + ((size_t)(b * 768 + n) << 14) + l0 + 2 * tm;
        #pragma unroll
        for (int i = 0; i < 4; i++) {
            float2 r = unpack2(acc2[i][j]);
            r.x += bb; r.y += bb;
            *(float2*)(op + 32 * i) = r;
        }
    }
}

// ---------------------------------------------------------------------------
// Depthwise 3x3 conv (taps at offsets -2..0), split x0/x1/v, vg = v*x1.
// ---------------------------------------------------------------------------
__global__ __launch_bounds__(256) void dwconv_kernel(
    const float* __restrict__ sfw, const float* __restrict__ sfb)
{
    const int bd = blockIdx.x;          // b*256 + d
    const int b = bd >> 8, d = bd & 255;
    const int tid = threadIdx.x;
    const int j = tid & 127;
    const size_t outp = (size_t)bd << 14;

    if (tid < 128) {
        const float* p = g_U + ((size_t)(b * 768 + d) << 14);
        float w[9];
        #pragma unroll
        for (int q = 0; q < 9; q++) w[q] = sfw[d * 9 + q];
        const float bs = sfb[d];
        float a0 = 0, a1 = 0, a2 = 0, r0 = 0, r1 = 0, r2 = 0;
        for (int i = 0; i < 128; i++) {
            const float* row = p + i * 128;
            float c0 = (j >= 2) ? row[j - 2] : 0.f;
            float c1 = (j >= 1) ? row[j - 1] : 0.f;
            float c2 = row[j];
            float acc = bs + w[0]*a0 + w[1]*a1 + w[2]*a2
                           + w[3]*r0 + w[4]*r1 + w[5]*r2
                           + w[6]*c0 + w[7]*c1 + w[8]*c2;
            g_x0[outp + i * 128 + j] = acc;
            a0 = r0; a1 = r1; a2 = r2; r0 = c0; r1 = c1; r2 = c2;
        }
    } else {
        const float* p1 = g_U + ((size_t)(b * 768 + 256 + d) << 14); // x1 src
        const float* p2 = g_U + ((size_t)(b * 768 + 512 + d) << 14); // v  src
        float w1[9], w2[9];
        #pragma unroll
        for (int q = 0; q < 9; q++) {
            w1[q] = sfw[(256 + d) * 9 + q];
            w2[q] = sfw[(512 + d) * 9 + q];
        }
        const float bs1 = sfb[256 + d], bs2 = sfb[512 + d];
        float a10=0,a11=0,a12=0, r10=0,r11=0,r12=0;
        float a20=0,a21=0,a22=0, r20=0,r21=0,r22=0;
        for (int i = 0; i < 128; i++) {
            const float* row1 = p1 + i * 128;
            const float* row2 = p2 + i * 128;
            float c10 = (j >= 2) ? row1[j - 2] : 0.f;
            float c11 = (j >= 1) ? row1[j - 1] : 0.f;
            float c12 = row1[j];
            float c20 = (j >= 2) ? row2[j - 2] : 0.f;
            float c21 = (j >= 1) ? row2[j - 1] : 0.f;
            float c22 = row2[j];
            float x1v = bs1 + w1[0]*a10 + w1[1]*a11 + w1[2]*a12
                            + w1[3]*r10 + w1[4]*r11 + w1[5]*r12
                            + w1[6]*c10 + w1[7]*c11 + w1[8]*c12;
            float vv  = bs2 + w2[0]*a20 + w2[1]*a21 + w2[2]*a22
                            + w2[3]*r20 + w2[4]*r21 + w2[5]*r22
                            + w2[6]*c20 + w2[7]*c21 + w2[8]*c22;
            g_vg[outp + i * 128 + j] = vv * x1v;
            a10=r10; a11=r11; a12=r12; r10=c10; r11=c11; r12=c12;
            a20=r20; a21=r21; a22=r22; r20=c20; r21=c21; r22=c22;
        }
    }
}

// ---------------------------------------------------------------------------
// Fused Toeplitz: per (b,d) plane in one CTA.
//   pass1: W1 = VG @ T(hy)      (W1 kept in smem, 64KB)
//   pass2: C  = T(hx) @ W1 ; g = (C + vg*fb) * x0
// Thread tile: m = tm + 16*ii (ii<8), n = 2*tn + 32*jj + {0,1} (jj<4 pairs).
// Dynamic smem: W1s[16384] | As[1024] | Ts[1024] | hxs[128] | hys[128]
// ---------------------------------------------------------------------------
#define TOEP_SMEM_FLOATS (16384 + 1024 + 1024 + 128 + 128)

__global__ __launch_bounds__(256) void toep_kernel(const float* __restrict__ fbias)
{
    extern __shared__ __align__(16) float sm[];
    float* W1s = sm;
    float* As  = sm + 16384;
    float* Ts  = sm + 17408;
    float* hxs = sm + 18432;
    float* hys = sm + 18560;

    const int bd = blockIdx.x;
    const int d = bd & 255;
    const int tid = threadIdx.x;
    const int tn = tid & 15, tm = tid >> 4;
    const int arow = tid >> 1, ak4 = (tid & 1) * 4;
    const float* Ap = g_vg + ((size_t)bd << 14);

    if (tid < 128) {
        hxs[tid] = g_hxT[d * 128 + tid];
        hys[tid] = g_hyT[d * 128 + tid];
    }

    unsigned long long acc2[8][4];
    #pragma unroll
    for (int i = 0; i < 8; i++)
        #pragma unroll
        for (int j = 0; j < 4; j++) acc2[i][j] = 0ULL;
    __syncthreads();

    // ---- pass 1: W1 = VG @ T(hy) ----
    for (int k0 = 0; k0 < 128; k0 += 8) {
        float4 av = *(const float4*)(Ap + arow * 128 + k0 + ak4);
        As[(ak4 + 0) * 128 + arow] = av.x;
        As[(ak4 + 1) * 128 + arow] = av.y;
        As[(ak4 + 2) * 128 + arow] = av.z;
        As[(ak4 + 3) * 128 + arow] = av.w;
        #pragma unroll
        for (int c = 0; c < 4; c++) {
            int e = tid * 4 + c;
            int ki = e >> 7, jj = e & 127;
            int lag = jj - k0 - ki;
            Ts[e] = (lag >= 0) ? hys[lag] : 0.f;
        }
        __syncthreads();
        #pragma unroll
        for (int k = 0; k < 8; k++) {
            unsigned long long b2[4];
            #pragma unroll
            for (int j = 0; j < 4; j++)
                b2[j] = *(const unsigned long long*)&Ts[k * 128 + 2 * tn + 32 * j];
            #pragma unroll
            for (int i = 0; i < 8; i++) {
                unsigned long long a2 = bcast2(As[k * 128 + tm + 16 * i]);
                #pragma unroll
                for (int j = 0; j < 4; j++) ffma2(acc2[i][j], a2, b2[j]);
            }
        }
        __syncthreads();
    }
    // write W1 to smem, reset acc
    #pragma unroll
    for (int i = 0; i < 8; i++)
        #pragma unroll
        for (int j = 0; j < 4; j++) {
            float2 r = unpack2(acc2[i][j]);
            *(float2*)&W1s[(tm + 16 * i) * 128 + 2 * tn + 32 * j] = r;
            acc2[i][j] = 0ULL;
        }
    __syncthreads();

    // ---- pass 2: C = T(hx) @ W1 ----
    for (int k0 = 0; k0 < 128; k0 += 8) {
        #pragma unroll
        for (int c = 0; c < 4; c++) {
            int e = tid * 4 + c;
            int ki = e >> 7, mm = e & 127;
            int lag = mm - k0 - ki;
            Ts[e] = (lag >= 0) ? hxs[lag] : 0.f;   // Ts[k][m] = hx[m-k]
        }
        __syncthreads();
        #pragma unroll
        for (int k = 0; k < 8; k++) {
            unsigned long long b2[4];
            #pragma unroll
            for (int j = 0; j < 4; j++)
                b2[j] = *(const unsigned long long*)&W1s[(k0 + k) * 128 + 2 * tn + 32 * j];
            #pragma unroll
            for (int i = 0; i < 8; i++) {
                unsigned long long a2 = bcast2(Ts[k * 128 + tm + 16 * i]);
                #pragma unroll
                for (int j = 0; j < 4; j++) ffma2(acc2[i][j], a2, b2[j]);
            }
        }
        __syncthreads();
    }
    // epilogue: g = (C + vg*fb) * x0
    const float fb = fbias[d];
    const float* x0p = g_x0 + ((size_t)bd << 14);
    float* gp = g_g + ((size_t)bd << 14);
    #pragma unroll
    for (int i = 0; i < 8; i++)
        #pragma unroll
        for (int j = 0; j < 4; j++) {
            int idx = (tm + 16 * i) * 128 + 2 * tn + 32 * j;
            float2 c = unpack2(acc2[i][j]);
            float2 v = *(const float2*)(Ap + idx);
            float2 x = *(const float2*)(x0p + idx);
            float2 r;
            r.x = (c.x + v.x * fb) * x.x;
            r.y = (c.y + v.y * fb) * x.y;
            *(float2*)(gp + idx) = r;
        }
}

// ---------------------------------------------------------------------------
// GEMM2: out(b,l,n) = g(b,d,l)^T @ out_w(d,n) + out_b.  A is K-major planar.
// Thread tile: m = tm + 16*ii (ii<8), n = 2*tn + 32*jj + {0,1} (jj<4 pairs).
// ---------------------------------------------------------------------------
__global__ __launch_bounds__(256) void gemm2_kernel(
    const float* __restrict__ W, const float* __restrict__ bias,
    float* __restrict__ Out)
{
    __shared__ __align__(16) float As[8 * 128];
    __shared__ __align__(16) float Bs[8 * 128];
    const int m0 = blockIdx.x * 128;
    const int n0 = blockIdx.y * 128;
    const int b  = blockIdx.z;
    const int tid = threadIdx.x;
    const int tn = tid & 15, tm = tid >> 4;
    const int akr = tid >> 5, am4 = (tid & 31) * 4;

    unsigned long long acc2[8][4];
    #pragma unroll
    for (int i = 0; i < 8; i++)
        #pragma unroll
        for (int j = 0; j < 4; j++) acc2[i][j] = 0ULL;

    const float* Ab = g_g + ((size_t)b << 22);
    for (int k0 = 0; k0 < 256; k0 += 8) {
        float4 av = *(const float4*)(Ab + ((size_t)(k0 + akr) << 14) + m0 + am4);
        *(float4*)(&As[akr * 128 + am4]) = av;
        float4 bv = *(const float4*)(W + (size_t)(k0 + akr) * 256 + n0 + am4);
        *(float4*)(&Bs[akr * 128 + am4]) = bv;
        __syncthreads();
        #pragma unroll
        for (int k = 0; k < 8; k++) {
            unsigned long long b2[4];
            #pragma unroll
            for (int j = 0; j < 4; j++)
                b2[j] = *(const unsigned long long*)&Bs[k * 128 + 2 * tn + 32 * j];
            #pragma unroll
            for (int i = 0; i < 8; i++) {
                unsigned long long a2 = bcast2(As[k * 128 + tm + 16 * i]);
                #pragma unroll
                for (int j = 0; j < 4; j++) ffma2(acc2[i][j], a2, b2[j]);
            }
        }
        __syncthreads();
    }
    #pragma unroll
    for (int j = 0; j < 4; j++) {
        int n = n0 + 2 * tn + 32 * j;
        float2 bb = *(const float2*)&bias[n];
        #pragma unroll
        for (int i = 0; i < 8; i++) {
            int m = m0 + tm + 16 * i;
            float2 r = unpack2(acc2[i][j]);
            r.x += bb.x; r.y += bb.y;
            *(float2*)&Out[(((size_t)b << 14) + m) * 256 + n] = r;
        }
    }
}

// ---------------------------------------------------------------------------
extern "C" void kernel_launch(void* const* d_in, const int* in_sizes, int n_in,
                              void* d_out, int out_size)
{
    (void)in_sizes; (void)n_in; (void)out_size;
    const float* x     = (const float*)d_in[0];
    const float* in_w  = (const float*)d_in[1];
    const float* in_b  = (const float*)d_in[2];
    const float* out_w = (const float*)d_in[3];
    const float* out_b = (const float*)d_in[4];
    const float* sf_w  = (const float*)d_in[5];
    const float* sf_b  = (const float*)d_in[6];
    const float* freq  = (const float*)d_in[7];
    const float* xw0 = (const float*)d_in[8];
    const float* xb0 = (const float*)d_in[9];
    const float* xw1 = (const float*)d_in[10];
    const float* xb1 = (const float*)d_in[11];
    const float* xw2 = (const float*)d_in[12];
    const float* xb2 = (const float*)d_in[13];
    const float* xw3 = (const float*)d_in[14];
    const float* yw0 = (const float*)d_in[15];
    const float* yb0 = (const float*)d_in[16];
    const float* yw1 = (const float*)d_in[17];
    const float* yb1 = (const float*)d_in[18];
    const float* yw2 = (const float*)d_in[19];
    const float* yb2 = (const float*)d_in[20];
    const float* yw3 = (const float*)d_in[21];
    const float* fbias = (const float*)d_in[22];
    float* out = (float*)d_out;

    filter_kernel<<<128, 64>>>(freq, xw0, xb0, xw1, xb1, xw2, xb2, xw3,
                               yw0, yb0, yw1, yb1, yw2, yb2, yw3);
    dim3 g1(512, 6);
    gemm1_kernel<<<g1, 256>>>(x, in_w, in_b);
    dwconv_kernel<<<1024, 256>>>(sf_w, sf_b);

    static bool attr_set = false;
    if (!attr_set) {
        cudaFuncSetAttribute(toep_kernel,
                             cudaFuncAttributeMaxDynamicSharedMemorySize,
                             TOEP_SMEM_FLOATS * sizeof(float));
        attr_set = true;
    }
    toep_kernel<<<1024, 256, TOEP_SMEM_FLOATS * sizeof(float)>>>(fbias);

    dim3 g2(128, 2, 4);
    gemm2_kernel<<<g2, 256>>>(out_w, out_b, out);
}

// round 5
// speedup vs baseline: 1.7515x; 1.5630x over previous
#include <cuda_runtime.h>
#include <cuda_bf16.h>
#include <cstdint>
#include <math.h>

// ---------------------------------------------------------------------------
// HyenaOperator2d:  B=4, S=128, D=256, d3=768, L=16384, FO=64
// All GEMM-shaped work on tensor cores via mma.sync bf16 with hi/lo split
// (3 MMAs per fp32 product: hi*hi + hi*lo + lo*hi).
//   filter_kernel : hx,hy (implicit MLP filters * decay), hx scaled 1/256
//   tprep         : Toeplitz T[r][c]=h[r-c] per d -> bf16 hi/lo (global)
//   xsplit        : x -> bf16 hi/lo
//   tsplit_*      : weights / g -> transposed bf16 hi/lo
//   gemm1_mma     : U = x @ in_w + in_b -> planar (b,c,l)
//   dwconv_kernel : depthwise 3x3 (taps -2..0), split, vg = v*x1 -> planar
//   toep_mma      : W1 = VG @ T(hy);  g = (T(hx) @ W1 + vg*fb)*x0
//   gemm2_mma     : out = gT @ out_w + out_b
// ---------------------------------------------------------------------------

#define PI_F 3.14159265358979f
#define MIN_D (-3.0701134573253943f)
#define MAX_D (-15.350567286626972f)

__device__ float g_hxT[256 * 128];            // [d][s], includes *dec*(1/256)
__device__ float g_hyT[256 * 128];            // [d][s], includes *dec
__device__ float g_U [50331648];              // (b,768,16384) planar
__device__ float g_x0[16777216];              // (b,256,16384) planar
__device__ float g_vg[16777216];
__device__ float g_g [16777216];              // toep output, planar (b,d,l)

__device__ __nv_bfloat16 g_xhi[65536 * 256];      // x split, row-major (m,k)
__device__ __nv_bfloat16 g_xlo[65536 * 256];
__device__ __nv_bfloat16 g_inwT_hi [768 * 256];   // [n][k]
__device__ __nv_bfloat16 g_inwT_lo [768 * 256];
__device__ __nv_bfloat16 g_outwT_hi[256 * 256];   // [n][k]
__device__ __nv_bfloat16 g_outwT_lo[256 * 256];
__device__ __nv_bfloat16 g_gT_hi[4 * 16384 * 256]; // (b,l,d)
__device__ __nv_bfloat16 g_gT_lo[4 * 16384 * 256];
__device__ __nv_bfloat16 g_Thx_hi[256 * 128 * 128]; // [d][r][c] = hx[r-c]
__device__ __nv_bfloat16 g_Thx_lo[256 * 128 * 128];
__device__ __nv_bfloat16 g_Thy_hi[256 * 128 * 128]; // [d][r][c] = hy[r-c]
__device__ __nv_bfloat16 g_Thy_lo[256 * 128 * 128];

// ---- helpers ---------------------------------------------------------------
__device__ __forceinline__ uint32_t smem_u32(const void* p) {
    uint32_t a;
    asm("{ .reg .u64 t; cvta.to.shared.u64 t, %1; cvt.u32.u64 %0, t; }"
        : "=r"(a) : "l"(p));
    return a;
}
__device__ __forceinline__ void split_bf16(float v, unsigned short& hi, unsigned short& lo) {
    __nv_bfloat16 h = __float2bfloat16(v);
    __nv_bfloat16 l = __float2bfloat16(v - __bfloat162float(h));
    hi = __bfloat16_as_ushort(h);
    lo = __bfloat16_as_ushort(l);
}
__device__ __forceinline__ void split4(float4 v, uint2& hv, uint2& lv) {
    unsigned short h0,h1,h2,h3,l0,l1,l2,l3;
    split_bf16(v.x, h0, l0); split_bf16(v.y, h1, l1);
    split_bf16(v.z, h2, l2); split_bf16(v.w, h3, l3);
    hv.x = ((uint32_t)h1 << 16) | h0;  hv.y = ((uint32_t)h3 << 16) | h2;
    lv.x = ((uint32_t)l1 << 16) | l0;  lv.y = ((uint32_t)l3 << 16) | l2;
}
__device__ __forceinline__ void ldsm4(uint32_t* r, uint32_t addr) {
    asm volatile("ldmatrix.sync.aligned.m8n8.x4.shared.b16 {%0,%1,%2,%3}, [%4];"
        : "=r"(r[0]), "=r"(r[1]), "=r"(r[2]), "=r"(r[3]) : "r"(addr));
}
__device__ __forceinline__ void mma_bf16(float* d, const uint32_t* a, const uint32_t* b) {
    asm volatile(
        "mma.sync.aligned.m16n8k16.row.col.f32.bf16.bf16.f32 "
        "{%0,%1,%2,%3}, {%4,%5,%6,%7}, {%8,%9}, {%0,%1,%2,%3};"
        : "+f"(d[0]), "+f"(d[1]), "+f"(d[2]), "+f"(d[3])
        : "r"(a[0]), "r"(a[1]), "r"(a[2]), "r"(a[3]), "r"(b[0]), "r"(b[1]));
}

// Warp-tile 64x32 split-bf16 MMA over a staged K panel (nk16 steps of k=16).
// Bases are smem byte addresses already offset to the warp's m/n origin.
// STRIDE = smem row stride in bytes (padded for conflict-free ldmatrix).
template <int STRIDE>
__device__ __forceinline__ void mma_panel(
    float acc[4][4][4],
    uint32_t ah, uint32_t al, uint32_t bh, uint32_t bl,
    int lane, int nk16)
{
    const int sub = lane >> 3, r = lane & 7;
    const int am = (sub & 1) * 8 + r;        // A: sub0/2 rows 0-7, sub1/3 rows 8-15
    const int ak = (sub >> 1) * 8;           //    sub2/3 k+8
    const int bn = (sub >> 1) * 8 + r;       // B: sub2/3 second n-tile
    const int bk = (sub & 1) * 8;            //    sub1/3 k+8
    for (int ks = 0; ks < nk16; ks++) {
        uint32_t AH[4][4], AL[4][4], BH[4][2], BL[4][2];
        #pragma unroll
        for (int mt = 0; mt < 4; mt++) {
            uint32_t off = (uint32_t)((mt * 16 + am) * STRIDE + (ks * 16 + ak) * 2);
            ldsm4(AH[mt], ah + off);
            ldsm4(AL[mt], al + off);
        }
        #pragma unroll
        for (int np = 0; np < 2; np++) {
            uint32_t u[4];
            uint32_t off = (uint32_t)((np * 16 + bn) * STRIDE + (ks * 16 + bk) * 2);
            ldsm4(u, bh + off);
            BH[2*np][0] = u[0]; BH[2*np][1] = u[1];
            BH[2*np+1][0] = u[2]; BH[2*np+1][1] = u[3];
            ldsm4(u, bl + off);
            BL[2*np][0] = u[0]; BL[2*np][1] = u[1];
            BL[2*np+1][0] = u[2]; BL[2*np+1][1] = u[3];
        }
        #pragma unroll
        for (int mt = 0; mt < 4; mt++)
            #pragma unroll
            for (int nt = 0; nt < 4; nt++) {
                mma_bf16(acc[mt][nt], AH[mt], BH[nt]);
                mma_bf16(acc[mt][nt], AH[mt], BL[nt]);
                mma_bf16(acc[mt][nt], AL[mt], BH[nt]);
            }
    }
}

// ---------------------------------------------------------------------------
// Implicit filter MLPs + positional embedding + decay. 128 blocks (s), 64 thr.
// ---------------------------------------------------------------------------
__global__ void filter_kernel(
    const float* __restrict__ freq,
    const float* __restrict__ xw0, const float* __restrict__ xb0,
    const float* __restrict__ xw1, const float* __restrict__ xb1,
    const float* __restrict__ xw2, const float* __restrict__ xb2,
    const float* __restrict__ xw3,
    const float* __restrict__ yw0, const float* __restrict__ yb0,
    const float* __restrict__ yw1, const float* __restrict__ yb1,
    const float* __restrict__ yw2, const float* __restrict__ yb2,
    const float* __restrict__ yw3)
{
    __shared__ float h[64];
    const int s = blockIdx.x;
    const int j = threadIdx.x;

    const float t   = (float)s / 127.0f;
    const float phi = 1e-4f * 2.0f * PI_F * (float)s / 128.0f;
    const float z0 = t, z1 = cosf(phi), z2 = -sinf(phi);
    const float fr = freq[j];

    for (int which = 0; which < 2; which++) {
        const float* w0 = which ? yw0 : xw0;  const float* b0 = which ? yb0 : xb0;
        const float* w1 = which ? yw1 : xw1;  const float* b1 = which ? yb1 : xb1;
        const float* w2 = which ? yw2 : xw2;  const float* b2 = which ? yb2 : xb2;
        const float* w3 = which ? yw3 : xw3;

        float v = z0 * w0[j] + z1 * w0[64 + j] + z2 * w0[128 + j] + b0[j];
        h[j] = sinf(fr * v);
        __syncthreads();

        float a = b1[j];
        #pragma unroll 8
        for (int k = 0; k < 64; k++) a += h[k] * w1[k * 64 + j];
        __syncthreads();
        h[j] = sinf(fr * a);
        __syncthreads();

        a = b2[j];
        #pragma unroll 8
        for (int k = 0; k < 64; k++) a += h[k] * w2[k * 64 + j];
        __syncthreads();
        h[j] = sinf(fr * a);
        __syncthreads();

        float o[4] = {0.f, 0.f, 0.f, 0.f};
        #pragma unroll 8
        for (int k = 0; k < 64; k++) {
            float hv = h[k];
            #pragma unroll
            for (int r = 0; r < 4; r++) o[r] += hv * w3[k * 256 + j + 64 * r];
        }
        #pragma unroll
        for (int r = 0; r < 4; r++) {
            int d = j + 64 * r;
            float delta = MIN_D + (MAX_D - MIN_D) * ((float)d / 255.0f);
            float dec = expf(-t * fabsf(delta));
            if (which == 0)
                g_hxT[d * 128 + s] = o[r] * dec * (1.0f / 256.0f);
            else
                g_hyT[d * 128 + s] = o[r] * dec;
        }
        __syncthreads();
    }
}

// ---------------------------------------------------------------------------
// Toeplitz precompute: T[r][c] = h[r-c] (0 if r<c), split hi/lo. 256 blocks.
// ---------------------------------------------------------------------------
__global__ __launch_bounds__(256) void tprep_kernel()
{
    __shared__ float hx[128], hy[128];
    const int d = blockIdx.x;
    const int tid = threadIdx.x;
    if (tid < 128) {
        hx[tid] = g_hxT[d * 128 + tid];
        hy[tid] = g_hyT[d * 128 + tid];
    }
    __syncthreads();
    const size_t base = (size_t)d * 16384;
    for (int e = tid; e < 16384; e += 256) {
        int r = e >> 7, c = e & 127;
        int lag = r - c;
        float vx = (lag >= 0) ? hx[lag] : 0.f;
        float vy = (lag >= 0) ? hy[lag] : 0.f;
        unsigned short xh, xl, yh, yl;
        split_bf16(vx, xh, xl);
        split_bf16(vy, yh, yl);
        g_Thx_hi[base + e] = __ushort_as_bfloat16(xh);
        g_Thx_lo[base + e] = __ushort_as_bfloat16(xl);
        g_Thy_hi[base + e] = __ushort_as_bfloat16(yh);
        g_Thy_lo[base + e] = __ushort_as_bfloat16(yl);
    }
}

// ---------------------------------------------------------------------------
// x -> bf16 hi/lo split (row-major, same layout).  grid 16384 x 256.
// ---------------------------------------------------------------------------
__global__ __launch_bounds__(256) void xsplit_kernel(const float* __restrict__ X)
{
    size_t i = (size_t)blockIdx.x * 256 + threadIdx.x;
    float4 v = *(const float4*)(X + i * 4);
    uint2 hv, lv;
    split4(v, hv, lv);
    *(uint2*)(g_xhi + i * 4) = hv;
    *(uint2*)(g_xlo + i * 4) = lv;
}

// ---------------------------------------------------------------------------
// Tiled transpose + bf16 hi/lo split: src[rows][cols] -> dst[cols][rows]
// ---------------------------------------------------------------------------
__device__ __forceinline__ void do_tsplit(
    const float* __restrict__ src, __nv_bfloat16* __restrict__ dhi,
    __nv_bfloat16* __restrict__ dlo, int rows, int cols)
{
    __shared__ float tile[32][33];
    const int c0 = blockIdx.x * 32, r0 = blockIdx.y * 32;
    const int tx = threadIdx.x, ty = threadIdx.y;
    #pragma unroll
    for (int i = 0; i < 4; i++)
        tile[ty + 8 * i][tx] = src[(size_t)(r0 + ty + 8 * i) * cols + c0 + tx];
    __syncthreads();
    #pragma unroll
    for (int i = 0; i < 4; i++) {
        float v = tile[tx][ty + 8 * i];
        unsigned short hi, lo;
        split_bf16(v, hi, lo);
        size_t o = (size_t)(c0 + ty + 8 * i) * rows + r0 + tx;
        dhi[o] = __ushort_as_bfloat16(hi);
        dlo[o] = __ushort_as_bfloat16(lo);
    }
}
__global__ void tsplit_inw_kernel(const float* __restrict__ w) {
    do_tsplit(w, g_inwT_hi, g_inwT_lo, 256, 768);
}
__global__ void tsplit_outw_kernel(const float* __restrict__ w) {
    do_tsplit(w, g_outwT_hi, g_outwT_lo, 256, 256);
}
__global__ void tsplit_g_kernel() {
    size_t plane = (size_t)256 * 16384;
    do_tsplit(g_g + blockIdx.z * plane, g_gT_hi + blockIdx.z * plane,
              g_gT_lo + blockIdx.z * plane, 256, 16384);
}

// ---------------------------------------------------------------------------
// GEMM1: U(b,c,l) = x @ in_w + in_b.  M=65536 K=256 N=768. grid(512,6).
// Stride-80B smem panels (conflict-free ldmatrix); epilogue staged -> planar.
// smem: AH/AL/BH/BL @ 0/10240/20480/30720 (40960); epilogue stg 128*129*4.
// ---------------------------------------------------------------------------
#define G1_SMEM 66048

__global__ __launch_bounds__(256) void gemm1_mma(const float* __restrict__ bias)
{
    extern __shared__ __align__(16) char sm[];
    const uint32_t smb = smem_u32(sm);
    const int tid = threadIdx.x, lane = tid & 31, wid = tid >> 5;
    const int wm = wid & 1, wn = wid >> 1;
    const int m0 = blockIdx.x * 128, n0 = blockIdx.y * 128;

    float acc[4][4][4];
    #pragma unroll
    for (int a = 0; a < 4; a++)
        #pragma unroll
        for (int b = 0; b < 4; b++)
            #pragma unroll
            for (int c = 0; c < 4; c++) acc[a][b][c] = 0.f;

    for (int kt = 0; kt < 8; kt++) {
        const int k0 = kt * 32;
        __syncthreads();
        #pragma unroll
        for (int e = tid; e < 512; e += 256) {
            int r = e >> 2, q = e & 3;
            size_t ga = (size_t)(m0 + r) * 256 + k0 + q * 8;
            *(uint4*)(sm +         r * 80 + q * 16) = *(const uint4*)(g_xhi + ga);
            *(uint4*)(sm + 10240 + r * 80 + q * 16) = *(const uint4*)(g_xlo + ga);
            size_t gb = (size_t)(n0 + r) * 256 + k0 + q * 8;
            *(uint4*)(sm + 20480 + r * 80 + q * 16) = *(const uint4*)(g_inwT_hi + gb);
            *(uint4*)(sm + 30720 + r * 80 + q * 16) = *(const uint4*)(g_inwT_lo + gb);
        }
        __syncthreads();
        mma_panel<80>(acc, smb + wm * 64 * 80, smb + 10240 + wm * 64 * 80,
                      smb + 20480 + wn * 32 * 80, smb + 30720 + wn * 32 * 80,
                      lane, 2);
    }

    // Epilogue: stage [m][n] in smem (stride 129), then coalesced planar write.
    __syncthreads();
    float* stg = (float*)sm;
    #pragma unroll
    for (int mt = 0; mt < 4; mt++)
        #pragma unroll
        for (int nt = 0; nt < 4; nt++) {
            int m = wm * 64 + mt * 16 + (lane >> 2);
            int n = wn * 32 + nt * 8 + 2 * (lane & 3);
            stg[m * 129 + n]           = acc[mt][nt][0];
            stg[m * 129 + n + 1]       = acc[mt][nt][1];
            stg[(m + 8) * 129 + n]     = acc[mt][nt][2];
            stg[(m + 8) * 129 + n + 1] = acc[mt][nt][3];
        }
    __syncthreads();
    const int b = m0 >> 14;
    const int l0 = m0 & 16383;
    const int mloc = tid & 63;
    #pragma unroll
    for (int j = 0; j < 32; j++) {
        int n = j * 4 + (tid >> 6);
        float bb = __ldg(bias + n0 + n);
        float* dst = g_U + ((size_t)(b * 768 + n0 + n) << 14) + l0;
        dst[mloc]      = stg[mloc * 129 + n] + bb;
        dst[mloc + 64] = stg[(mloc + 64) * 129 + n] + bb;
    }
}

// ---------------------------------------------------------------------------
// GEMM2: out(b,l,n) = gT(b,l,d) @ out_wT + out_b.  grid(128,2,4).
// ---------------------------------------------------------------------------
#define G2_SMEM 40960

__global__ __launch_bounds__(256) void gemm2_mma(
    const float* __restrict__ bias, float* __restrict__ Out)
{
    extern __shared__ __align__(16) char sm[];
    const uint32_t smb = smem_u32(sm);
    const int tid = threadIdx.x, lane = tid & 31, wid = tid >> 5;
    const int wm = wid & 1, wn = wid >> 1;
    const int m0 = blockIdx.x * 128, n0 = blockIdx.y * 128;
    const int b = blockIdx.z;
    const size_t abase = ((size_t)b << 14) * 256;

    float acc[4][4][4];
    #pragma unroll
    for (int a = 0; a < 4; a++)
        #pragma unroll
        for (int c = 0; c < 4; c++)
            #pragma unroll
            for (int e = 0; e < 4; e++) acc[a][c][e] = 0.f;

    for (int kt = 0; kt < 8; kt++) {
        const int k0 = kt * 32;
        __syncthreads();
        #pragma unroll
        for (int e = tid; e < 512; e += 256) {
            int r = e >> 2, q = e & 3;
            size_t ga = abase + (size_t)(m0 + r) * 256 + k0 + q * 8;
            *(uint4*)(sm +         r * 80 + q * 16) = *(const uint4*)(g_gT_hi + ga);
            *(uint4*)(sm + 10240 + r * 80 + q * 16) = *(const uint4*)(g_gT_lo + ga);
            size_t gb = (size_t)(n0 + r) * 256 + k0 + q * 8;
            *(uint4*)(sm + 20480 + r * 80 + q * 16) = *(const uint4*)(g_outwT_hi + gb);
            *(uint4*)(sm + 30720 + r * 80 + q * 16) = *(const uint4*)(g_outwT_lo + gb);
        }
        __syncthreads();
        mma_panel<80>(acc, smb + wm * 64 * 80, smb + 10240 + wm * 64 * 80,
                      smb + 20480 + wn * 32 * 80, smb + 30720 + wn * 32 * 80,
                      lane, 2);
    }

    // Direct row-major stores (float2 = 2 consecutive n).
    #pragma unroll
    for (int mt = 0; mt < 4; mt++)
        #pragma unroll
        for (int nt = 0; nt < 4; nt++) {
            int m = m0 + wm * 64 + mt * 16 + (lane >> 2);
            int n = n0 + wn * 32 + nt * 8 + 2 * (lane & 3);
            float2 bb = *(const float2*)&bias[n];
            float2 v0 = { acc[mt][nt][0] + bb.x, acc[mt][nt][1] + bb.y };
            float2 v1 = { acc[mt][nt][2] + bb.x, acc[mt][nt][3] + bb.y };
            *(float2*)&Out[(((size_t)b << 14) + m) * 256 + n] = v0;
            *(float2*)&Out[(((size_t)b << 14) + m + 8) * 256 + n] = v1;
        }
}

// ---------------------------------------------------------------------------
// Depthwise 3x3 conv (taps at offsets -2..0), split x0/x1/v, vg = v*x1.
// ---------------------------------------------------------------------------
__global__ __launch_bounds__(256) void dwconv_kernel(
    const float* __restrict__ sfw, const float* __restrict__ sfb)
{
    const int bd = blockIdx.x;
    const int b = bd >> 8, d = bd & 255;
    const int tid = threadIdx.x;
    const int j = tid & 127;
    const size_t outp = (size_t)bd << 14;

    if (tid < 128) {
        const float* p = g_U + ((size_t)(b * 768 + d) << 14);
        float w[9];
        #pragma unroll
        for (int q = 0; q < 9; q++) w[q] = sfw[d * 9 + q];
        const float bs = sfb[d];
        float a0 = 0, a1 = 0, a2 = 0, r0 = 0, r1 = 0, r2 = 0;
        for (int i = 0; i < 128; i++) {
            const float* row = p + i * 128;
            float c0 = (j >= 2) ? row[j - 2] : 0.f;
            float c1 = (j >= 1) ? row[j - 1] : 0.f;
            float c2 = row[j];
            float acc = bs + w[0]*a0 + w[1]*a1 + w[2]*a2
                           + w[3]*r0 + w[4]*r1 + w[5]*r2
                           + w[6]*c0 + w[7]*c1 + w[8]*c2;
            g_x0[outp + i * 128 + j] = acc;
            a0 = r0; a1 = r1; a2 = r2; r0 = c0; r1 = c1; r2 = c2;
        }
    } else {
        const float* p1 = g_U + ((size_t)(b * 768 + 256 + d) << 14);
        const float* p2 = g_U + ((size_t)(b * 768 + 512 + d) << 14);
        float w1[9], w2[9];
        #pragma unroll
        for (int q = 0; q < 9; q++) {
            w1[q] = sfw[(256 + d) * 9 + q];
            w2[q] = sfw[(512 + d) * 9 + q];
        }
        const float bs1 = sfb[256 + d], bs2 = sfb[512 + d];
        float a10=0,a11=0,a12=0, r10=0,r11=0,r12=0;
        float a20=0,a21=0,a22=0, r20=0,r21=0,r22=0;
        for (int i = 0; i < 128; i++) {
            const float* row1 = p1 + i * 128;
            const float* row2 = p2 + i * 128;
            float c10 = (j >= 2) ? row1[j - 2] : 0.f;
            float c11 = (j >= 1) ? row1[j - 1] : 0.f;
            float c12 = row1[j];
            float c20 = (j >= 2) ? row2[j - 2] : 0.f;
            float c21 = (j >= 1) ? row2[j - 1] : 0.f;
            float c22 = row2[j];
            float x1v = bs1 + w1[0]*a10 + w1[1]*a11 + w1[2]*a12
                            + w1[3]*r10 + w1[4]*r11 + w1[5]*r12
                            + w1[6]*c10 + w1[7]*c11 + w1[8]*c12;
            float vv  = bs2 + w2[0]*a20 + w2[1]*a21 + w2[2]*a22
                            + w2[3]*r20 + w2[4]*r21 + w2[5]*r22
                            + w2[6]*c20 + w2[7]*c21 + w2[8]*c22;
            g_vg[outp + i * 128 + j] = vv * x1v;
            a10=r10; a11=r11; a12=r12; r10=c10; r11=c11; r12=c12;
            a20=r20; a21=r21; a22=r22; r20=c20; r21=c21; r22=c22;
        }
    }
}

// ---------------------------------------------------------------------------
// Fused Toeplitz on tensor cores: one CTA per (b,d) plane.
//   pass1: W1 = VG @ T(hy);  W1^T staged in smem fp32 (stride 132)
//   pass2: C = T(hx) @ W1;   g = (C + vg*fb) * x0
// smem: AH/AL/BH/BL stride 272B (128 rows) @ 0/34816/69632/104448;
//       stg fp32 128*132*4 @ 139264.  Total 206848.
// ---------------------------------------------------------------------------
#define TP_AH 0
#define TP_AL 34816
#define TP_BH 69632
#define TP_BL 104448
#define TP_STG 139264
#define TP_SMEM 206848

__global__ __launch_bounds__(256) void toep_mma(const float* __restrict__ fbias)
{
    extern __shared__ __align__(16) char sm[];
    const uint32_t smb = smem_u32(sm);
    const int tid = threadIdx.x, lane = tid & 31, wid = tid >> 5;
    const int wm = wid & 1, wn = wid >> 1;
    const int bd = blockIdx.x;
    const int d = bd & 255;
    const float* vgp = g_vg + ((size_t)bd << 14);
    const size_t tbase = (size_t)d * 16384;

    // stage pass1: A = VG (fp32 -> split), B = Thy[d] (precomputed bf16)
    #pragma unroll
    for (int e = tid; e < 4096; e += 256) {
        int r = e >> 5, q = e & 31;
        float4 v = *(const float4*)(vgp + r * 128 + q * 4);
        uint2 hv, lv;
        split4(v, hv, lv);
        *(uint2*)(sm + TP_AH + r * 272 + q * 8) = hv;
        *(uint2*)(sm + TP_AL + r * 272 + q * 8) = lv;
    }
    #pragma unroll
    for (int e = tid; e < 2048; e += 256) {
        int r = e >> 4, q = e & 15;
        size_t gi = tbase + r * 128 + q * 8;
        *(uint4*)(sm + TP_BH + r * 272 + q * 16) = *(const uint4*)(g_Thy_hi + gi);
        *(uint4*)(sm + TP_BL + r * 272 + q * 16) = *(const uint4*)(g_Thy_lo + gi);
    }
    __syncthreads();

    float acc[4][4][4];
    #pragma unroll
    for (int a = 0; a < 4; a++)
        #pragma unroll
        for (int b = 0; b < 4; b++)
            #pragma unroll
            for (int c = 0; c < 4; c++) acc[a][b][c] = 0.f;

    mma_panel<272>(acc, smb + TP_AH + wm * 64 * 272, smb + TP_AL + wm * 64 * 272,
                   smb + TP_BH + wn * 32 * 272, smb + TP_BL + wn * 32 * 272,
                   lane, 8);
    __syncthreads();

    // store W1 transposed: stg[j][h] (j = n, h = m), stride 132
    float* stg = (float*)(sm + TP_STG);
    #pragma unroll
    for (int mt = 0; mt < 4; mt++)
        #pragma unroll
        for (int nt = 0; nt < 4; nt++) {
            int m = wm * 64 + mt * 16 + (lane >> 2);
            int n = wn * 32 + nt * 8 + 2 * (lane & 3);
            stg[n * 132 + m]           = acc[mt][nt][0];
            stg[(n + 1) * 132 + m]     = acc[mt][nt][1];
            stg[n * 132 + m + 8]       = acc[mt][nt][2];
            stg[(n + 1) * 132 + m + 8] = acc[mt][nt][3];
            acc[mt][nt][0] = acc[mt][nt][1] = acc[mt][nt][2] = acc[mt][nt][3] = 0.f;
        }
    __syncthreads();

    // restage pass2: A = Thx[d], B = split(W1^T)
    #pragma unroll
    for (int e = tid; e < 2048; e += 256) {
        int r = e >> 4, q = e & 15;
        size_t gi = tbase + r * 128 + q * 8;
        *(uint4*)(sm + TP_AH + r * 272 + q * 16) = *(const uint4*)(g_Thx_hi + gi);
        *(uint4*)(sm + TP_AL + r * 272 + q * 16) = *(const uint4*)(g_Thx_lo + gi);
    }
    #pragma unroll
    for (int e = tid; e < 4096; e += 256) {
        int j = e >> 5, q = e & 31;
        float4 v = *(const float4*)(stg + j * 132 + q * 4);
        uint2 hv, lv;
        split4(v, hv, lv);
        *(uint2*)(sm + TP_BH + j * 272 + q * 8) = hv;
        *(uint2*)(sm + TP_BL + j * 272 + q * 8) = lv;
    }
    __syncthreads();

    mma_panel<272>(acc, smb + TP_AH + wm * 64 * 272, smb + TP_AL + wm * 64 * 272,
                   smb + TP_BH + wn * 32 * 272, smb + TP_BL + wn * 32 * 272,
                   lane, 8);

    // epilogue: g = (C + vg*fb) * x0
    const float fb = fbias[d];
    const float* x0p = g_x0 + ((size_t)bd << 14);
    float* gp = g_g + ((size_t)bd << 14);
    #pragma unroll
    for (int mt = 0; mt < 4; mt++)
        #pragma unroll
        for (int nt = 0; nt < 4; nt++) {
            int m = wm * 64 + mt * 16 + (lane >> 2);
            int n = wn * 32 + nt * 8 + 2 * (lane & 3);
            #pragma unroll
            for (int half = 0; half < 2; half++) {
                int idx = (m + 8 * half) * 128 + n;
                float2 c = { acc[mt][nt][2 * half], acc[mt][nt][2 * half + 1] };
                float2 v = *(const float2*)(vgp + idx);
                float2 x = *(const float2*)(x0p + idx);
                float2 r;
                r.x = (c.x + v.x * fb) * x.x;
                r.y = (c.y + v.y * fb) * x.y;
                *(float2*)(gp + idx) = r;
            }
        }
}

// ---------------------------------------------------------------------------
extern "C" void kernel_launch(void* const* d_in, const int* in_sizes, int n_in,
                              void* d_out, int out_size)
{
    (void)in_sizes; (void)n_in; (void)out_size;
    const float* x     = (const float*)d_in[0];
    const float* in_w  = (const float*)d_in[1];
    const float* in_b  = (const float*)d_in[2];
    const float* out_w = (const float*)d_in[3];
    const float* out_b = (const float*)d_in[4];
    const float* sf_w  = (const float*)d_in[5];
    const float* sf_b  = (const float*)d_in[6];
    const float* freq  = (const float*)d_in[7];
    const float* xw0 = (const float*)d_in[8];
    const float* xb0 = (const float*)d_in[9];
    const float* xw1 = (const float*)d_in[10];
    const float* xb1 = (const float*)d_in[11];
    const float* xw2 = (const float*)d_in[12];
    const float* xb2 = (const float*)d_in[13];
    const float* xw3 = (const float*)d_in[14];
    const float* yw0 = (const float*)d_in[15];
    const float* yb0 = (const float*)d_in[16];
    const float* yw1 = (const float*)d_in[17];
    const float* yb1 = (const float*)d_in[18];
    const float* yw2 = (const float*)d_in[19];
    const float* yb2 = (const float*)d_in[20];
    const float* yw3 = (const float*)d_in[21];
    const float* fbias = (const float*)d_in[22];
    float* out = (float*)d_out;

    cudaFuncSetAttribute(gemm1_mma, cudaFuncAttributeMaxDynamicSharedMemorySize, G1_SMEM);
    cudaFuncSetAttribute(gemm2_mma, cudaFuncAttributeMaxDynamicSharedMemorySize, G2_SMEM);
    cudaFuncSetAttribute(toep_mma,  cudaFuncAttributeMaxDynamicSharedMemorySize, TP_SMEM);

    filter_kernel<<<128, 64>>>(freq, xw0, xb0, xw1, xb1, xw2, xb2, xw3,
                               yw0, yb0, yw1, yb1, yw2, yb2, yw3);
    tprep_kernel<<<256, 256>>>();
    xsplit_kernel<<<16384, 256>>>(x);
    dim3 tb(32, 8);
    tsplit_inw_kernel<<<dim3(24, 8), tb>>>(in_w);
    tsplit_outw_kernel<<<dim3(8, 8), tb>>>(out_w);

    dim3 g1(512, 6);
    gemm1_mma<<<g1, 256, G1_SMEM>>>(in_b);

    dwconv_kernel<<<1024, 256>>>(sf_w, sf_b);
    toep_mma<<<1024, 256, TP_SMEM>>>(fbias);

    tsplit_g_kernel<<<dim3(512, 8, 4), tb>>>();

    dim3 g2(128, 2, 4);
    gemm2_mma<<<g2, 256, G2_SMEM>>>(out_b, out);
}

// round 6
// speedup vs baseline: 2.1020x; 1.2001x over previous
#include <cuda_runtime.h>
#include <cuda_bf16.h>
#include <cstdint>
#include <math.h>

// ---------------------------------------------------------------------------
// HyenaOperator2d:  B=4, S=128, D=256, d3=768, L=16384, FO=64
// Tensor-core mma.sync bf16 with hi/lo split (3 MMAs per fp32 product).
//   filter_kernel : hx,hy (implicit MLP filters * decay), hx scaled 1/256
//   tsplit_*      : weights -> transposed bf16 hi/lo
//   gemm1_mma     : U = x @ in_w + in_b -> planar (b,c,l)   (splits x inline)
//   dwconv_kernel : depthwise 3x3 (taps -2..0), split, vg = v*x1 -> planar
//   toep_mma      : W1 = VG @ T(hy);  g = (T(hx) @ W1 + vg*fb)*x0
//                   (Toeplitz generated in-kernel, W1 split in smem)
//   gemm2_mma     : out = gT @ out_w + out_b   (splits+transposes g inline)
// ---------------------------------------------------------------------------

#define PI_F 3.14159265358979f
#define MIN_D (-3.0701134573253943f)
#define MAX_D (-15.350567286626972f)

__device__ float g_hxT[256 * 128];            // [d][s], includes *dec*(1/256)
__device__ float g_hyT[256 * 128];            // [d][s], includes *dec
__device__ float g_U [50331648];              // (b,768,16384) planar
__device__ float g_x0[16777216];              // (b,256,16384) planar
__device__ float g_vg[16777216];
__device__ float g_g [16777216];              // toep output, planar (b,d,l)

__device__ __nv_bfloat16 g_inwT_hi [768 * 256];   // [n][k]
__device__ __nv_bfloat16 g_inwT_lo [768 * 256];
__device__ __nv_bfloat16 g_outwT_hi[256 * 256];   // [n][k]
__device__ __nv_bfloat16 g_outwT_lo[256 * 256];

// ---- helpers ---------------------------------------------------------------
__device__ __forceinline__ uint32_t smem_u32(const void* p) {
    uint32_t a;
    asm("{ .reg .u64 t; cvta.to.shared.u64 t, %1; cvt.u32.u64 %0, t; }"
        : "=r"(a) : "l"(p));
    return a;
}
__device__ __forceinline__ void split_bf16(float v, unsigned short& hi, unsigned short& lo) {
    __nv_bfloat16 h = __float2bfloat16(v);
    __nv_bfloat16 l = __float2bfloat16(v - __bfloat162float(h));
    hi = __bfloat16_as_ushort(h);
    lo = __bfloat16_as_ushort(l);
}
__device__ __forceinline__ void split4(float4 v, uint2& hv, uint2& lv) {
    unsigned short h0,h1,h2,h3,l0,l1,l2,l3;
    split_bf16(v.x, h0, l0); split_bf16(v.y, h1, l1);
    split_bf16(v.z, h2, l2); split_bf16(v.w, h3, l3);
    hv.x = ((uint32_t)h1 << 16) | h0;  hv.y = ((uint32_t)h3 << 16) | h2;
    lv.x = ((uint32_t)l1 << 16) | l0;  lv.y = ((uint32_t)l3 << 16) | l2;
}
__device__ __forceinline__ void ldsm4(uint32_t* r, uint32_t addr) {
    asm volatile("ldmatrix.sync.aligned.m8n8.x4.shared.b16 {%0,%1,%2,%3}, [%4];"
        : "=r"(r[0]), "=r"(r[1]), "=r"(r[2]), "=r"(r[3]) : "r"(addr));
}
__device__ __forceinline__ void mma_bf16(float* d, const uint32_t* a, const uint32_t* b) {
    asm volatile(
        "mma.sync.aligned.m16n8k16.row.col.f32.bf16.bf16.f32 "
        "{%0,%1,%2,%3}, {%4,%5,%6,%7}, {%8,%9}, {%0,%1,%2,%3};"
        : "+f"(d[0]), "+f"(d[1]), "+f"(d[2]), "+f"(d[3])
        : "r"(a[0]), "r"(a[1]), "r"(a[2]), "r"(a[3]), "r"(b[0]), "r"(b[1]));
}

// Warp-tile 64x32 split-bf16 MMA over staged K panel (nk16 steps of k=16).
template <int STRIDE>
__device__ __forceinline__ void mma_panel(
    float acc[4][4][4],
    uint32_t ah, uint32_t al, uint32_t bh, uint32_t bl,
    int lane, int nk16)
{
    const int sub = lane >> 3, r = lane & 7;
    const int am = (sub & 1) * 8 + r;
    const int ak = (sub >> 1) * 8;
    const int bn = (sub >> 1) * 8 + r;
    const int bk = (sub & 1) * 8;
    for (int ks = 0; ks < nk16; ks++) {
        uint32_t AH[4][4], AL[4][4], BH[4][2], BL[4][2];
        #pragma unroll
        for (int mt = 0; mt < 4; mt++) {
            uint32_t off = (uint32_t)((mt * 16 + am) * STRIDE + (ks * 16 + ak) * 2);
            ldsm4(AH[mt], ah + off);
            ldsm4(AL[mt], al + off);
        }
        #pragma unroll
        for (int np = 0; np < 2; np++) {
            uint32_t u[4];
            uint32_t off = (uint32_t)((np * 16 + bn) * STRIDE + (ks * 16 + bk) * 2);
            ldsm4(u, bh + off);
            BH[2*np][0] = u[0]; BH[2*np][1] = u[1];
            BH[2*np+1][0] = u[2]; BH[2*np+1][1] = u[3];
            ldsm4(u, bl + off);
            BL[2*np][0] = u[0]; BL[2*np][1] = u[1];
            BL[2*np+1][0] = u[2]; BL[2*np+1][1] = u[3];
        }
        #pragma unroll
        for (int mt = 0; mt < 4; mt++)
            #pragma unroll
            for (int nt = 0; nt < 4; nt++) {
                mma_bf16(acc[mt][nt], AH[mt], BH[nt]);
                mma_bf16(acc[mt][nt], AH[mt], BL[nt]);
                mma_bf16(acc[mt][nt], AL[mt], BH[nt]);
            }
    }
}

// ---------------------------------------------------------------------------
// Implicit filter MLPs + positional embedding + decay. 128 blocks (s), 64 thr.
// ---------------------------------------------------------------------------
__global__ void filter_kernel(
    const float* __restrict__ freq,
    const float* __restrict__ xw0, const float* __restrict__ xb0,
    const float* __restrict__ xw1, const float* __restrict__ xb1,
    const float* __restrict__ xw2, const float* __restrict__ xb2,
    const float* __restrict__ xw3,
    const float* __restrict__ yw0, const float* __restrict__ yb0,
    const float* __restrict__ yw1, const float* __restrict__ yb1,
    const float* __restrict__ yw2, const float* __restrict__ yb2,
    const float* __restrict__ yw3)
{
    __shared__ float h[64];
    const int s = blockIdx.x;
    const int j = threadIdx.x;

    const float t   = (float)s / 127.0f;
    const float phi = 1e-4f * 2.0f * PI_F * (float)s / 128.0f;
    const float z0 = t, z1 = cosf(phi), z2 = -sinf(phi);
    const float fr = freq[j];

    for (int which = 0; which < 2; which++) {
        const float* w0 = which ? yw0 : xw0;  const float* b0 = which ? yb0 : xb0;
        const float* w1 = which ? yw1 : xw1;  const float* b1 = which ? yb1 : xb1;
        const float* w2 = which ? yw2 : xw2;  const float* b2 = which ? yb2 : xb2;
        const float* w3 = which ? yw3 : xw3;

        float v = z0 * w0[j] + z1 * w0[64 + j] + z2 * w0[128 + j] + b0[j];
        h[j] = sinf(fr * v);
        __syncthreads();

        float a = b1[j];
        #pragma unroll 8
        for (int k = 0; k < 64; k++) a += h[k] * w1[k * 64 + j];
        __syncthreads();
        h[j] = sinf(fr * a);
        __syncthreads();

        a = b2[j];
        #pragma unroll 8
        for (int k = 0; k < 64; k++) a += h[k] * w2[k * 64 + j];
        __syncthreads();
        h[j] = sinf(fr * a);
        __syncthreads();

        float o[4] = {0.f, 0.f, 0.f, 0.f};
        #pragma unroll 8
        for (int k = 0; k < 64; k++) {
            float hv = h[k];
            #pragma unroll
            for (int r = 0; r < 4; r++) o[r] += hv * w3[k * 256 + j + 64 * r];
        }
        #pragma unroll
        for (int r = 0; r < 4; r++) {
            int d = j + 64 * r;
            float delta = MIN_D + (MAX_D - MIN_D) * ((float)d / 255.0f);
            float dec = expf(-t * fabsf(delta));
            if (which == 0)
                g_hxT[d * 128 + s] = o[r] * dec * (1.0f / 256.0f);
            else
                g_hyT[d * 128 + s] = o[r] * dec;
        }
        __syncthreads();
    }
}

// ---------------------------------------------------------------------------
// Tiled transpose + bf16 hi/lo split for weights.
// ---------------------------------------------------------------------------
__device__ __forceinline__ void do_tsplit(
    const float* __restrict__ src, __nv_bfloat16* __restrict__ dhi,
    __nv_bfloat16* __restrict__ dlo, int rows, int cols)
{
    __shared__ float tile[32][33];
    const int c0 = blockIdx.x * 32, r0 = blockIdx.y * 32;
    const int tx = threadIdx.x, ty = threadIdx.y;
    #pragma unroll
    for (int i = 0; i < 4; i++)
        tile[ty + 8 * i][tx] = src[(size_t)(r0 + ty + 8 * i) * cols + c0 + tx];
    __syncthreads();
    #pragma unroll
    for (int i = 0; i < 4; i++) {
        float v = tile[tx][ty + 8 * i];
        unsigned short hi, lo;
        split_bf16(v, hi, lo);
        size_t o = (size_t)(c0 + ty + 8 * i) * rows + r0 + tx;
        dhi[o] = __ushort_as_bfloat16(hi);
        dlo[o] = __ushort_as_bfloat16(lo);
    }
}
__global__ void tsplit_inw_kernel(const float* __restrict__ w) {
    do_tsplit(w, g_inwT_hi, g_inwT_lo, 256, 768);
}
__global__ void tsplit_outw_kernel(const float* __restrict__ w) {
    do_tsplit(w, g_outwT_hi, g_outwT_lo, 256, 256);
}

// ---------------------------------------------------------------------------
// GEMM1: U(b,c,l) = x @ in_w + in_b.  M=65536 K=256 N=768. grid(512,6).
// A split from fp32 x inline. Stride-80B panels; staged planar epilogue.
// ---------------------------------------------------------------------------
#define G1_SMEM 66048

__global__ __launch_bounds__(256) void gemm1_mma(
    const float* __restrict__ X, const float* __restrict__ bias)
{
    extern __shared__ __align__(16) char sm[];
    const uint32_t smb = smem_u32(sm);
    const int tid = threadIdx.x, lane = tid & 31, wid = tid >> 5;
    const int wm = wid & 1, wn = wid >> 1;
    const int m0 = blockIdx.x * 128, n0 = blockIdx.y * 128;

    float acc[4][4][4];
    #pragma unroll
    for (int a = 0; a < 4; a++)
        #pragma unroll
        for (int b = 0; b < 4; b++)
            #pragma unroll
            for (int c = 0; c < 4; c++) acc[a][b][c] = 0.f;

    for (int kt = 0; kt < 8; kt++) {
        const int k0 = kt * 32;
        __syncthreads();
        // A: split x fp32 -> hi/lo (128 rows x 32 k)
        #pragma unroll
        for (int e = tid; e < 1024; e += 256) {
            int r = e >> 3, q = e & 7;
            float4 v = *(const float4*)(X + (size_t)(m0 + r) * 256 + k0 + q * 4);
            uint2 hv, lv;
            split4(v, hv, lv);
            *(uint2*)(sm +         r * 80 + q * 8) = hv;
            *(uint2*)(sm + 10240 + r * 80 + q * 8) = lv;
        }
        // B: precomputed in_wT hi/lo
        #pragma unroll
        for (int e = tid; e < 512; e += 256) {
            int r = e >> 2, q = e & 3;
            size_t gb = (size_t)(n0 + r) * 256 + k0 + q * 8;
            *(uint4*)(sm + 20480 + r * 80 + q * 16) = *(const uint4*)(g_inwT_hi + gb);
            *(uint4*)(sm + 30720 + r * 80 + q * 16) = *(const uint4*)(g_inwT_lo + gb);
        }
        __syncthreads();
        mma_panel<80>(acc, smb + wm * 64 * 80, smb + 10240 + wm * 64 * 80,
                      smb + 20480 + wn * 32 * 80, smb + 30720 + wn * 32 * 80,
                      lane, 2);
    }

    __syncthreads();
    float* stg = (float*)sm;
    #pragma unroll
    for (int mt = 0; mt < 4; mt++)
        #pragma unroll
        for (int nt = 0; nt < 4; nt++) {
            int m = wm * 64 + mt * 16 + (lane >> 2);
            int n = wn * 32 + nt * 8 + 2 * (lane & 3);
            stg[m * 129 + n]           = acc[mt][nt][0];
            stg[m * 129 + n + 1]       = acc[mt][nt][1];
            stg[(m + 8) * 129 + n]     = acc[mt][nt][2];
            stg[(m + 8) * 129 + n + 1] = acc[mt][nt][3];
        }
    __syncthreads();
    const int b = m0 >> 14;
    const int l0 = m0 & 16383;
    const int mloc = tid & 63;
    #pragma unroll
    for (int j = 0; j < 32; j++) {
        int n = j * 4 + (tid >> 6);
        float bb = __ldg(bias + n0 + n);
        float* dst = g_U + ((size_t)(b * 768 + n0 + n) << 14) + l0;
        dst[mloc]      = stg[mloc * 129 + n] + bb;
        dst[mloc + 64] = stg[(mloc + 64) * 129 + n] + bb;
    }
}

// ---------------------------------------------------------------------------
// GEMM2: out(b,l,n) = g(b,d,l)^T @ out_wT + out_b.  grid(128,2,4).
// A split+transposed from fp32 planar g inline.
// ---------------------------------------------------------------------------
#define G2_SMEM 40960

__global__ __launch_bounds__(256) void gemm2_mma(
    const float* __restrict__ bias, float* __restrict__ Out)
{
    extern __shared__ __align__(16) char sm[];
    const uint32_t smb = smem_u32(sm);
    const int tid = threadIdx.x, lane = tid & 31, wid = tid >> 5;
    const int wm = wid & 1, wn = wid >> 1;
    const int m0 = blockIdx.x * 128, n0 = blockIdx.y * 128;
    const int b = blockIdx.z;
    const float* Gb = g_g + ((size_t)b << 22);

    float acc[4][4][4];
    #pragma unroll
    for (int a = 0; a < 4; a++)
        #pragma unroll
        for (int c = 0; c < 4; c++)
            #pragma unroll
            for (int e = 0; e < 4; e++) acc[a][c][e] = 0.f;

    for (int kt = 0; kt < 8; kt++) {
        const int k0 = kt * 32;
        __syncthreads();
        // A: transpose+split from planar g: A[m=l][k=d]
        #pragma unroll
        for (int e = tid; e < 1024; e += 256) {
            int lloc = e & 127, dq = e >> 7;     // dq: 4 d's per thread
            unsigned short h[4], l[4];
            #pragma unroll
            for (int t = 0; t < 4; t++) {
                float v = Gb[((size_t)(k0 + dq * 4 + t) << 14) + m0 + lloc];
                split_bf16(v, h[t], l[t]);
            }
            uint2 hv, lv;
            hv.x = ((uint32_t)h[1] << 16) | h[0];  hv.y = ((uint32_t)h[3] << 16) | h[2];
            lv.x = ((uint32_t)l[1] << 16) | l[0];  lv.y = ((uint32_t)l[3] << 16) | l[2];
            *(uint2*)(sm +         lloc * 80 + dq * 8) = hv;
            *(uint2*)(sm + 10240 + lloc * 80 + dq * 8) = lv;
        }
        // B: precomputed out_wT hi/lo
        #pragma unroll
        for (int e = tid; e < 512; e += 256) {
            int r = e >> 2, q = e & 3;
            size_t gb = (size_t)(n0 + r) * 256 + k0 + q * 8;
            *(uint4*)(sm + 20480 + r * 80 + q * 16) = *(const uint4*)(g_outwT_hi + gb);
            *(uint4*)(sm + 30720 + r * 80 + q * 16) = *(const uint4*)(g_outwT_lo + gb);
        }
        __syncthreads();
        mma_panel<80>(acc, smb + wm * 64 * 80, smb + 10240 + wm * 64 * 80,
                      smb + 20480 + wn * 32 * 80, smb + 30720 + wn * 32 * 80,
                      lane, 2);
    }

    #pragma unroll
    for (int mt = 0; mt < 4; mt++)
        #pragma unroll
        for (int nt = 0; nt < 4; nt++) {
            int m = m0 + wm * 64 + mt * 16 + (lane >> 2);
            int n = n0 + wn * 32 + nt * 8 + 2 * (lane & 3);
            float2 bb = *(const float2*)&bias[n];
            float2 v0 = { acc[mt][nt][0] + bb.x, acc[mt][nt][1] + bb.y };
            float2 v1 = { acc[mt][nt][2] + bb.x, acc[mt][nt][3] + bb.y };
            *(float2*)&Out[(((size_t)b << 14) + m) * 256 + n] = v0;
            *(float2*)&Out[(((size_t)b << 14) + m + 8) * 256 + n] = v1;
        }
}

// ---------------------------------------------------------------------------
// Depthwise 3x3 conv, float4 + shfl. grid 2048 x 32 threads.
// block = (bd, which): which=0 -> x0 plane; which=1 -> x1 & v planes -> vg.
// ---------------------------------------------------------------------------
__device__ __forceinline__ float4 hconv(float4 c, float m1, float m2,
                                        float w0, float w1, float w2) {
    float4 o;
    o.x = w0 * m2  + w1 * m1  + w2 * c.x;
    o.y = w0 * m1  + w1 * c.x + w2 * c.y;
    o.z = w0 * c.x + w1 * c.y + w2 * c.z;
    o.w = w0 * c.y + w1 * c.z + w2 * c.w;
    return o;
}
__device__ __forceinline__ void lnbr(float4 c, int lane, float& m1, float& m2) {
    m1 = __shfl_up_sync(0xFFFFFFFFu, c.w, 1);
    m2 = __shfl_up_sync(0xFFFFFFFFu, c.z, 1);
    if (lane == 0) { m1 = 0.f; m2 = 0.f; }
}

__global__ __launch_bounds__(32) void dwconv_kernel(
    const float* __restrict__ sfw, const float* __restrict__ sfb)
{
    const int bd = blockIdx.x >> 1;
    const int which = blockIdx.x & 1;
    const int b = bd >> 8, d = bd & 255;
    const int lane = threadIdx.x;
    const size_t outp = (size_t)bd << 14;

    if (which == 0) {
        const float* p = g_U + ((size_t)(b * 768 + d) << 14);
        float w[9];
        #pragma unroll
        for (int q = 0; q < 9; q++) w[q] = sfw[d * 9 + q];
        const float bs = sfb[d];
        float4 av = {0,0,0,0}, rv = {0,0,0,0};
        float am1 = 0, am2 = 0, rm1 = 0, rm2 = 0;
        for (int i = 0; i < 128; i++) {
            float4 cv = *(const float4*)(p + i * 128 + lane * 4);
            float cm1, cm2;
            lnbr(cv, lane, cm1, cm2);
            float4 o = hconv(av, am1, am2, w[0], w[1], w[2]);
            float4 o2 = hconv(rv, rm1, rm2, w[3], w[4], w[5]);
            float4 o3 = hconv(cv, cm1, cm2, w[6], w[7], w[8]);
            float4 r;
            r.x = bs + o.x + o2.x + o3.x;
            r.y = bs + o.y + o2.y + o3.y;
            r.z = bs + o.z + o2.z + o3.z;
            r.w = bs + o.w + o2.w + o3.w;
            *(float4*)(g_x0 + outp + i * 128 + lane * 4) = r;
            av = rv; am1 = rm1; am2 = rm2;
            rv = cv; rm1 = cm1; rm2 = cm2;
        }
    } else {
        const float* p1 = g_U + ((size_t)(b * 768 + 256 + d) << 14);
        const float* p2 = g_U + ((size_t)(b * 768 + 512 + d) << 14);
        float w1[9], w2[9];
        #pragma unroll
        for (int q = 0; q < 9; q++) {
            w1[q] = sfw[(256 + d) * 9 + q];
            w2[q] = sfw[(512 + d) * 9 + q];
        }
        const float bs1 = sfb[256 + d], bs2 = sfb[512 + d];
        float4 av1 = {0,0,0,0}, rv1 = {0,0,0,0}, av2 = {0,0,0,0}, rv2 = {0,0,0,0};
        float am11=0, am12=0, rm11=0, rm12=0, am21=0, am22=0, rm21=0, rm22=0;
        for (int i = 0; i < 128; i++) {
            float4 cv1 = *(const float4*)(p1 + i * 128 + lane * 4);
            float4 cv2 = *(const float4*)(p2 + i * 128 + lane * 4);
            float cm11, cm12, cm21, cm22;
            lnbr(cv1, lane, cm11, cm12);
            lnbr(cv2, lane, cm21, cm22);
            float4 oa = hconv(av1, am11, am12, w1[0], w1[1], w1[2]);
            float4 ob = hconv(rv1, rm11, rm12, w1[3], w1[4], w1[5]);
            float4 oc = hconv(cv1, cm11, cm12, w1[6], w1[7], w1[8]);
            float4 pa = hconv(av2, am21, am22, w2[0], w2[1], w2[2]);
            float4 pb = hconv(rv2, rm21, rm22, w2[3], w2[4], w2[5]);
            float4 pc = hconv(cv2, cm21, cm22, w2[6], w2[7], w2[8]);
            float4 r;
            r.x = (bs1 + oa.x + ob.x + oc.x) * (bs2 + pa.x + pb.x + pc.x);
            r.y = (bs1 + oa.y + ob.y + oc.y) * (bs2 + pa.y + pb.y + pc.y);
            r.z = (bs1 + oa.z + ob.z + oc.z) * (bs2 + pa.z + pb.z + pc.z);
            r.w = (bs1 + oa.w + ob.w + oc.w) * (bs2 + pa.w + pb.w + pc.w);
            *(float4*)(g_vg + outp + i * 128 + lane * 4) = r;
            av1 = rv1; am11 = rm11; am12 = rm12;
            rv1 = cv1; rm11 = cm11; rm12 = cm12;
            av2 = rv2; am21 = rm21; am22 = rm22;
            rv2 = cv2; rm21 = cm21; rm22 = cm22;
        }
    }
}

// ---------------------------------------------------------------------------
// Fused Toeplitz on tensor cores; Toeplitz generated in-kernel.
// smem: AH/AL/BH/BL stride 272B @ 0/34816/69632/104448; hx/hy @ 139264.
// ---------------------------------------------------------------------------
#define TP_AH 0
#define TP_AL 34816
#define TP_BH 69632
#define TP_BL 104448
#define TP_HV 139264
#define TP_SMEM 140288

__global__ __launch_bounds__(256) void toep_mma(const float* __restrict__ fbias)
{
    extern __shared__ __align__(16) char sm[];
    const uint32_t smb = smem_u32(sm);
    float* hxs = (float*)(sm + TP_HV);
    float* hys = hxs + 128;
    const int tid = threadIdx.x, lane = tid & 31, wid = tid >> 5;
    const int wm = wid & 1, wn = wid >> 1;
    const int bd = blockIdx.x;
    const int d = bd & 255;
    const float* vgp = g_vg + ((size_t)bd << 14);

    if (tid < 128) {
        hxs[tid] = g_hxT[d * 128 + tid];
        hys[tid] = g_hyT[d * 128 + tid];
    }
    __syncthreads();

    // stage pass1: A = split(VG), B[r][c] = hy[r-c] generated
    #pragma unroll
    for (int e = tid; e < 4096; e += 256) {
        int r = e >> 5, q = e & 31;
        float4 v = *(const float4*)(vgp + r * 128 + q * 4);
        uint2 hv, lv;
        split4(v, hv, lv);
        *(uint2*)(sm + TP_AH + r * 272 + q * 8) = hv;
        *(uint2*)(sm + TP_AL + r * 272 + q * 8) = lv;
    }
    #pragma unroll
    for (int e = tid; e < 4096; e += 256) {
        int r = e >> 5, c4 = (e & 31) * 4;
        float4 v;
        v.x = (r - c4     >= 0) ? hys[r - c4]     : 0.f;
        v.y = (r - c4 - 1 >= 0) ? hys[r - c4 - 1] : 0.f;
        v.z = (r - c4 - 2 >= 0) ? hys[r - c4 - 2] : 0.f;
        v.w = (r - c4 - 3 >= 0) ? hys[r - c4 - 3] : 0.f;
        uint2 hv, lv;
        split4(v, hv, lv);
        *(uint2*)(sm + TP_BH + r * 272 + c4 * 2) = hv;
        *(uint2*)(sm + TP_BL + r * 272 + c4 * 2) = lv;
    }
    __syncthreads();

    float acc[4][4][4];
    #pragma unroll
    for (int a = 0; a < 4; a++)
        #pragma unroll
        for (int b = 0; b < 4; b++)
            #pragma unroll
            for (int c = 0; c < 4; c++) acc[a][b][c] = 0.f;

    mma_panel<272>(acc, smb + TP_AH + wm * 64 * 272, smb + TP_AL + wm * 64 * 272,
                   smb + TP_BH + wn * 32 * 272, smb + TP_BL + wn * 32 * 272,
                   lane, 8);
    __syncthreads();   // everyone done reading B before overwrite

    // W1^T split directly into B buffers: B[n=j][k=h] = W1[h][j]
    __nv_bfloat16* bh = (__nv_bfloat16*)(sm + TP_BH);
    __nv_bfloat16* bl = (__nv_bfloat16*)(sm + TP_BL);
    #pragma unroll
    for (int mt = 0; mt < 4; mt++)
        #pragma unroll
        for (int nt = 0; nt < 4; nt++) {
            int m = wm * 64 + mt * 16 + (lane >> 2);
            int n = wn * 32 + nt * 8 + 2 * (lane & 3);
            unsigned short h, l;
            split_bf16(acc[mt][nt][0], h, l);
            bh[n * 136 + m] = __ushort_as_bfloat16(h);
            bl[n * 136 + m] = __ushort_as_bfloat16(l);
            split_bf16(acc[mt][nt][1], h, l);
            bh[(n + 1) * 136 + m] = __ushort_as_bfloat16(h);
            bl[(n + 1) * 136 + m] = __ushort_as_bfloat16(l);
            split_bf16(acc[mt][nt][2], h, l);
            bh[n * 136 + m + 8] = __ushort_as_bfloat16(h);
            bl[n * 136 + m + 8] = __ushort_as_bfloat16(l);
            split_bf16(acc[mt][nt][3], h, l);
            bh[(n + 1) * 136 + m + 8] = __ushort_as_bfloat16(h);
            bl[(n + 1) * 136 + m + 8] = __ushort_as_bfloat16(l);
            acc[mt][nt][0] = acc[mt][nt][1] = acc[mt][nt][2] = acc[mt][nt][3] = 0.f;
        }

    // restage A: A[m][k] = hx[m-k] generated
    #pragma unroll
    for (int e = tid; e < 4096; e += 256) {
        int r = e >> 5, c4 = (e & 31) * 4;
        float4 v;
        v.x = (r - c4     >= 0) ? hxs[r - c4]     : 0.f;
        v.y = (r - c4 - 1 >= 0) ? hxs[r - c4 - 1] : 0.f;
        v.z = (r - c4 - 2 >= 0) ? hxs[r - c4 - 2] : 0.f;
        v.w = (r - c4 - 3 >= 0) ? hxs[r - c4 - 3] : 0.f;
        uint2 hv, lv;
        split4(v, hv, lv);
        *(uint2*)(sm + TP_AH + r * 272 + c4 * 2) = hv;
        *(uint2*)(sm + TP_AL + r * 272 + c4 * 2) = lv;
    }
    __syncthreads();

    mma_panel<272>(acc, smb + TP_AH + wm * 64 * 272, smb + TP_AL + wm * 64 * 272,
                   smb + TP_BH + wn * 32 * 272, smb + TP_BL + wn * 32 * 272,
                   lane, 8);

    // epilogue: g = (C + vg*fb) * x0
    const float fb = fbias[d];
    const float* x0p = g_x0 + ((size_t)bd << 14);
    float* gp = g_g + ((size_t)bd << 14);
    #pragma unroll
    for (int mt = 0; mt < 4; mt++)
        #pragma unroll
        for (int nt = 0; nt < 4; nt++) {
            int m = wm * 64 + mt * 16 + (lane >> 2);
            int n = wn * 32 + nt * 8 + 2 * (lane & 3);
            #pragma unroll
            for (int half = 0; half < 2; half++) {
                int idx = (m + 8 * half) * 128 + n;
                float2 c = { acc[mt][nt][2 * half], acc[mt][nt][2 * half + 1] };
                float2 v = *(const float2*)(vgp + idx);
                float2 x = *(const float2*)(x0p + idx);
                float2 r;
                r.x = (c.x + v.x * fb) * x.x;
                r.y = (c.y + v.y * fb) * x.y;
                *(float2*)(gp + idx) = r;
            }
        }
}

// ---------------------------------------------------------------------------
extern "C" void kernel_launch(void* const* d_in, const int* in_sizes, int n_in,
                              void* d_out, int out_size)
{
    (void)in_sizes; (void)n_in; (void)out_size;
    const float* x     = (const float*)d_in[0];
    const float* in_w  = (const float*)d_in[1];
    const float* in_b  = (const float*)d_in[2];
    const float* out_w = (const float*)d_in[3];
    const float* out_b = (const float*)d_in[4];
    const float* sf_w  = (const float*)d_in[5];
    const float* sf_b  = (const float*)d_in[6];
    const float* freq  = (const float*)d_in[7];
    const float* xw0 = (const float*)d_in[8];
    const float* xb0 = (const float*)d_in[9];
    const float* xw1 = (const float*)d_in[10];
    const float* xb1 = (const float*)d_in[11];
    const float* xw2 = (const float*)d_in[12];
    const float* xb2 = (const float*)d_in[13];
    const float* xw3 = (const float*)d_in[14];
    const float* yw0 = (const float*)d_in[15];
    const float* yb0 = (const float*)d_in[16];
    const float* yw1 = (const float*)d_in[17];
    const float* yb1 = (const float*)d_in[18];
    const float* yw2 = (const float*)d_in[19];
    const float* yb2 = (const float*)d_in[20];
    const float* yw3 = (const float*)d_in[21];
    const float* fbias = (const float*)d_in[22];
    float* out = (float*)d_out;

    cudaFuncSetAttribute(gemm1_mma, cudaFuncAttributeMaxDynamicSharedMemorySize, G1_SMEM);
    cudaFuncSetAttribute(gemm2_mma, cudaFuncAttributeMaxDynamicSharedMemorySize, G2_SMEM);
    cudaFuncSetAttribute(toep_mma,  cudaFuncAttributeMaxDynamicSharedMemorySize, TP_SMEM);

    filter_kernel<<<128, 64>>>(freq, xw0, xb0, xw1, xb1, xw2, xb2, xw3,
                               yw0, yb0, yw1, yb1, yw2, yb2, yw3);
    dim3 tb(32, 8);
    tsplit_inw_kernel<<<dim3(24, 8), tb>>>(in_w);
    tsplit_outw_kernel<<<dim3(8, 8), tb>>>(out_w);

    dim3 g1(512, 6);
    gemm1_mma<<<g1, 256, G1_SMEM>>>(x, in_b);

    dwconv_kernel<<<2048, 32>>>(sf_w, sf_b);
    toep_mma<<<1024, 256, TP_SMEM>>>(fbias);

    dim3 g2(128, 2, 4);
    gemm2_mma<<<g2, 256, G2_SMEM>>>(out_b, out);
}